// round 2
// baseline (speedup 1.0000x reference)
#include <cuda_runtime.h>
#include <cuda_bf16.h>
#include <math.h>

// Problem constants (fixed shapes for this problem instance)
#define MAX_N 500000
#define HDIM  64

// Scratch (device globals — no allocation allowed)
__device__ float g_h0[(size_t)MAX_N * HDIM];   // transformed features (message source)
__device__ float g_h1[(size_t)MAX_N * HDIM];   // aggregation accumulator / layer output
__device__ float g_dinv[MAX_N];                // deg -> rsqrt(deg)
__device__ float g_pool[HDIM];                 // global mean-pool accumulator

// ---------------- degree / normalization ----------------
__global__ void k_init_deg(int N) {
    int i = blockIdx.x * blockDim.x + threadIdx.x;
    if (i < N) g_dinv[i] = 1.0f;  // self-loop contributes 1 to in-degree
}

__global__ void k_count_deg(const int* __restrict__ ei, int E) {
    int e = blockIdx.x * blockDim.x + threadIdx.x;
    if (e < E) {
        int d = ei[E + e];   // dst row
        atomicAdd(&g_dinv[d], 1.0f);
    }
}

__global__ void k_rsqrt_deg(int N) {
    int i = blockIdx.x * blockDim.x + threadIdx.x;
    if (i < N) g_dinv[i] = rsqrtf(g_dinv[i]);
}

// ---------------- layer 1 transform: h0 = x @ W1  (N x 3 @ 3 x 64) ----------------
__global__ void k_transform1(const float* __restrict__ x, const float* __restrict__ W1, int N) {
    int idx = blockIdx.x * blockDim.x + threadIdx.x;
    if (idx >= N * HDIM) return;
    int n = idx >> 6;
    int c = idx & 63;
    float x0 = x[(size_t)n * 3 + 0];
    float x1 = x[(size_t)n * 3 + 1];
    float x2 = x[(size_t)n * 3 + 2];
    g_h0[idx] = x0 * W1[c] + x1 * W1[64 + c] + x2 * W1[128 + c];
}

// ---------------- aggregation init: h1 = b + selfloop(h0) ----------------
__global__ void k_agg_init(const float* __restrict__ b, int N) {
    int idx = blockIdx.x * blockDim.x + threadIdx.x;
    if (idx >= N * HDIM) return;
    int n = idx >> 6;
    int c = idx & 63;
    float di = g_dinv[n];
    g_h1[idx] = b[c] + g_h0[idx] * di * di;
}

// ---------------- edge aggregation: one warp per edge ----------------
__global__ void k_agg_edges(const int* __restrict__ ei, int E) {
    int warp = (blockIdx.x * blockDim.x + threadIdx.x) >> 5;
    int lane = threadIdx.x & 31;
    if (warp >= E) return;
    int s = ei[warp];
    int d = ei[E + warp];
    float coef = g_dinv[s] * g_dinv[d];
    const float* hs = g_h0 + (size_t)s * HDIM;
    float*       hd = g_h1 + (size_t)d * HDIM;
    atomicAdd(&hd[lane],      hs[lane]      * coef);
    atomicAdd(&hd[lane + 32], hs[lane + 32] * coef);
}

// ---------------- 64x64 transform with input relu: h0 = relu(h1) @ W ----------------
// block = 256 threads, 32 nodes per block
// thread mapping: n = tid>>3 (0..31), c8 = tid&7 (8 output channels each)
__global__ __launch_bounds__(256) void k_transform64(const float* __restrict__ W, int N) {
    __shared__ float sW[64 * 64];      // 16 KB
    __shared__ float sh[32 * 65];      // padded, conflict-free column reads
    int tid = threadIdx.x;
    int nodeBase = blockIdx.x * 32;

    #pragma unroll
    for (int i = tid; i < 4096; i += 256) sW[i] = W[i];

    for (int i = tid; i < 2048; i += 256) {
        int n = i >> 6, c = i & 63;
        float v = 0.0f;
        if (nodeBase + n < N) v = fmaxf(g_h1[(size_t)(nodeBase + n) * HDIM + c], 0.0f);
        sh[n * 65 + c] = v;
    }
    __syncthreads();

    int n  = tid >> 3;
    int c8 = tid & 7;
    float acc0 = 0.f, acc1 = 0.f, acc2 = 0.f, acc3 = 0.f;
    float acc4 = 0.f, acc5 = 0.f, acc6 = 0.f, acc7 = 0.f;

    const float* shrow = &sh[n * 65];
    #pragma unroll
    for (int k = 0; k < 64; k++) {
        float hv = shrow[k];
        float4 wa = *(const float4*)&sW[k * 64 + c8 * 8];
        float4 wb = *(const float4*)&sW[k * 64 + c8 * 8 + 4];
        acc0 += hv * wa.x; acc1 += hv * wa.y; acc2 += hv * wa.z; acc3 += hv * wa.w;
        acc4 += hv * wb.x; acc5 += hv * wb.y; acc6 += hv * wb.z; acc7 += hv * wb.w;
    }

    if (nodeBase + n < N) {
        float* o = g_h0 + (size_t)(nodeBase + n) * HDIM + c8 * 8;
        *(float4*)o       = make_float4(acc0, acc1, acc2, acc3);
        *((float4*)o + 1) = make_float4(acc4, acc5, acc6, acc7);
    }
}

// ---------------- pooling ----------------
__global__ void k_zero_pool() {
    if (threadIdx.x < HDIM) g_pool[threadIdx.x] = 0.0f;
}

__global__ void k_pool(int N) {
    __shared__ float sdata[256];
    int tid = threadIdx.x;
    size_t total = (size_t)N * HDIM;
    size_t stride = (size_t)gridDim.x * blockDim.x;   // multiple of 64 by construction
    float local = 0.0f;
    for (size_t i = (size_t)blockIdx.x * blockDim.x + tid; i < total; i += stride)
        local += fmaxf(g_h1[i], 0.0f);
    sdata[tid] = local;
    __syncthreads();
    if (tid < 64) {
        float s = sdata[tid] + sdata[tid + 64] + sdata[tid + 128] + sdata[tid + 192];
        atomicAdd(&g_pool[tid], s);
    }
}

// ---------------- final FC + tanh: out[24] ----------------
__global__ void k_final(const float* __restrict__ Wfc, const float* __restrict__ bfc,
                        float* __restrict__ out, int N) {
    int c = threadIdx.x;
    if (c >= 24) return;
    float invN = 1.0f / (float)N;
    float acc = bfc[c];
    #pragma unroll
    for (int k = 0; k < 64; k++)
        acc += (g_pool[k] * invN) * Wfc[k * 24 + c];
    out[c] = tanhf(acc);
}

// ---------------- launch ----------------
extern "C" void kernel_launch(void* const* d_in, const int* in_sizes, int n_in,
                              void* d_out, int out_size) {
    const float* x   = (const float*)d_in[0];
    const int*   ei  = (const int*)d_in[1];   // JAX default x64-disabled => int32
    // d_in[2] = batch (all zeros, single graph) — unused
    const float* W1  = (const float*)d_in[3];
    const float* b1  = (const float*)d_in[4];
    const float* W2  = (const float*)d_in[5];
    const float* b2  = (const float*)d_in[6];
    const float* W3  = (const float*)d_in[7];
    const float* b3  = (const float*)d_in[8];
    const float* Wfc = (const float*)d_in[9];
    const float* bfc = (const float*)d_in[10];
    float* out = (float*)d_out;

    int N = in_sizes[0] / 3;
    int E = in_sizes[1] / 2;

    const int T = 256;
    int nBlocksN   = (N + T - 1) / T;
    int nBlocksE   = (E + T - 1) / T;
    int nBlocksNC  = (N * HDIM + T - 1) / T;      // 32M/256 = 125000
    int nBlocksTr  = (N + 31) / 32;               // 32 nodes per block
    int nBlocksAgg = (int)(((size_t)E * 32 + T - 1) / T);

    // normalization coefficients
    k_init_deg<<<nBlocksN, T>>>(N);
    k_count_deg<<<nBlocksE, T>>>(ei, E);
    k_rsqrt_deg<<<nBlocksN, T>>>(N);

    // layer 1
    k_transform1<<<nBlocksNC, T>>>(x, W1, N);
    k_agg_init<<<nBlocksNC, T>>>(b1, N);
    k_agg_edges<<<nBlocksAgg, T>>>(ei, E);

    // layer 2
    k_transform64<<<nBlocksTr, T>>>(W2, N);
    k_agg_init<<<nBlocksNC, T>>>(b2, N);
    k_agg_edges<<<nBlocksAgg, T>>>(ei, E);

    // layer 3
    k_transform64<<<nBlocksTr, T>>>(W3, N);
    k_agg_init<<<nBlocksNC, T>>>(b3, N);
    k_agg_edges<<<nBlocksAgg, T>>>(ei, E);

    // global mean pool + FC + tanh
    k_zero_pool<<<1, 64>>>();
    k_pool<<<2048, T>>>(N);
    k_final<<<1, 32>>>(Wfc, bfc, out, N);
}

// round 3
// speedup vs baseline: 2.0818x; 2.0818x over previous
#include <cuda_runtime.h>
#include <cuda_bf16.h>
#include <math.h>

#define MAX_N 500000
#define MAX_E 1000000
#define HDIM  64
#define SCAN_T 512          // threads per scan block
#define SCAN_ITEMS 1024     // elements per scan block (2 per thread)

// ---------------- device scratch (no allocation allowed) ----------------
__device__ float g_h0[(size_t)MAX_N * HDIM];     // scaled messages (dinv * transform out)
__device__ float g_h1[(size_t)MAX_N * HDIM];     // layer output (post-aggregate, pre-relu)
__device__ float g_dinv[MAX_N];
__device__ float g_xs[(size_t)MAX_N * 3];        // dinv-scaled input features
__device__ float g_xa[(size_t)MAX_N * 3];        // aggregated input features (ÂX)
__device__ int   g_degi[MAX_N];
__device__ int   g_rowptr[MAX_N + 1];
__device__ int   g_cursor[MAX_N];
__device__ int   g_esrc[MAX_E];
__device__ int   g_bsum[1024];
__device__ float g_pool[HDIM];

// ---------------- f32x2 packed helpers (Blackwell FFMA2) ----------------
__device__ __forceinline__ unsigned long long pack2(float a, float b) {
    unsigned long long r;
    asm("mov.b64 %0, {%1, %2};" : "=l"(r) : "f"(a), "f"(b));
    return r;
}
__device__ __forceinline__ void fma2(unsigned long long& d, unsigned long long a, unsigned long long b) {
    asm("fma.rn.f32x2 %0, %1, %2, %0;" : "+l"(d) : "l"(a), "l"(b));
}
__device__ __forceinline__ float2 unpack2(unsigned long long v) {
    float2 f;
    asm("mov.b64 {%0, %1}, %2;" : "=f"(f.x), "=f"(f.y) : "l"(v));
    return f;
}

// ---------------- degree / prep ----------------
__global__ void k_zero(int N) {
    int i = blockIdx.x * blockDim.x + threadIdx.x;
    if (i < N) { g_degi[i] = 0; g_cursor[i] = 0; }
}

__global__ void k_hist(const int* __restrict__ ei, int E) {
    int e = blockIdx.x * blockDim.x + threadIdx.x;
    if (e < E) atomicAdd(&g_degi[ei[E + e]], 1);
}

// dinv = rsqrt(deg+1); xs = dinv * x
__global__ void k_prep(const float* __restrict__ x, int N) {
    int i = blockIdx.x * blockDim.x + threadIdx.x;
    if (i >= N) return;
    float di = rsqrtf((float)(g_degi[i] + 1));
    g_dinv[i] = di;
    g_xs[(size_t)i * 3 + 0] = di * x[(size_t)i * 3 + 0];
    g_xs[(size_t)i * 3 + 1] = di * x[(size_t)i * 3 + 1];
    g_xs[(size_t)i * 3 + 2] = di * x[(size_t)i * 3 + 2];
}

// ---------------- exclusive scan of g_degi -> g_rowptr ----------------
__global__ __launch_bounds__(SCAN_T) void k_scan_local(int N) {
    __shared__ int sdata[SCAN_T];
    int base = blockIdx.x * SCAN_ITEMS;
    int i0 = base + threadIdx.x * 2;
    int d0 = (i0     < N) ? g_degi[i0]     : 0;
    int d1 = (i0 + 1 < N) ? g_degi[i0 + 1] : 0;
    int tsum = d0 + d1;
    sdata[threadIdx.x] = tsum;
    __syncthreads();
    for (int off = 1; off < SCAN_T; off <<= 1) {
        int v = (threadIdx.x >= off) ? sdata[threadIdx.x - off] : 0;
        __syncthreads();
        sdata[threadIdx.x] += v;
        __syncthreads();
    }
    int excl = sdata[threadIdx.x] - tsum;   // exclusive within block
    if (i0     < N) g_rowptr[i0]     = excl;
    if (i0 + 1 < N) g_rowptr[i0 + 1] = excl + d0;
    if (threadIdx.x == SCAN_T - 1) g_bsum[blockIdx.x] = sdata[SCAN_T - 1];
}

__global__ __launch_bounds__(SCAN_T) void k_scan_bsums(int B) {
    __shared__ int sdata[SCAN_T];
    int v = (threadIdx.x < B) ? g_bsum[threadIdx.x] : 0;
    sdata[threadIdx.x] = v;
    __syncthreads();
    for (int off = 1; off < SCAN_T; off <<= 1) {
        int p = (threadIdx.x >= off) ? sdata[threadIdx.x - off] : 0;
        __syncthreads();
        sdata[threadIdx.x] += p;
        __syncthreads();
    }
    if (threadIdx.x < B) g_bsum[threadIdx.x] = sdata[threadIdx.x] - v;  // exclusive
}

__global__ void k_scan_add(int N, int E) {
    int i = blockIdx.x * blockDim.x + threadIdx.x;
    if (i < N) g_rowptr[i] += g_bsum[i / SCAN_ITEMS];
    if (i == 0) g_rowptr[N] = E;
}

__global__ void k_fill(const int* __restrict__ ei, int E) {
    int e = blockIdx.x * blockDim.x + threadIdx.x;
    if (e >= E) return;
    int s = ei[e];
    int d = ei[E + e];
    int pos = g_rowptr[d] + atomicAdd(&g_cursor[d], 1);
    g_esrc[pos] = s;
}

// ---------------- layer 1: aggregate x (3-wide), then h1 = xa @ W1 + b1 ----------------
__global__ void k_agg_x(int N) {
    int d = blockIdx.x * blockDim.x + threadIdx.x;
    if (d >= N) return;
    float a0 = g_xs[(size_t)d * 3 + 0];
    float a1 = g_xs[(size_t)d * 3 + 1];
    float a2 = g_xs[(size_t)d * 3 + 2];
    int beg = g_rowptr[d], end = g_rowptr[d + 1];
    for (int i = beg; i < end; i++) {
        int s = g_esrc[i];
        a0 += g_xs[(size_t)s * 3 + 0];
        a1 += g_xs[(size_t)s * 3 + 1];
        a2 += g_xs[(size_t)s * 3 + 2];
    }
    float di = g_dinv[d];
    g_xa[(size_t)d * 3 + 0] = di * a0;
    g_xa[(size_t)d * 3 + 1] = di * a1;
    g_xa[(size_t)d * 3 + 2] = di * a2;
}

// one thread per node, 64 channels -> 16 float4 stores
__global__ __launch_bounds__(256) void k_l1(const float* __restrict__ W1,
                                            const float* __restrict__ b1, int N) {
    __shared__ float sW[3 * 64];
    __shared__ float sb[64];
    int tid = threadIdx.x;
    if (tid < 192) sW[tid] = W1[tid];
    if (tid < 64)  sb[tid] = b1[tid];
    __syncthreads();
    int n = blockIdx.x * blockDim.x + tid;
    if (n >= N) return;
    float x0 = g_xa[(size_t)n * 3 + 0];
    float x1 = g_xa[(size_t)n * 3 + 1];
    float x2 = g_xa[(size_t)n * 3 + 2];
    float* o = g_h1 + (size_t)n * HDIM;
    #pragma unroll
    for (int c = 0; c < 64; c += 4) {
        float4 v;
        v.x = sb[c+0] + x0 * sW[c+0] + x1 * sW[64+c+0] + x2 * sW[128+c+0];
        v.y = sb[c+1] + x0 * sW[c+1] + x1 * sW[64+c+1] + x2 * sW[128+c+1];
        v.z = sb[c+2] + x0 * sW[c+2] + x1 * sW[64+c+2] + x2 * sW[128+c+2];
        v.w = sb[c+3] + x0 * sW[c+3] + x1 * sW[64+c+3] + x2 * sW[128+c+3];
        *(float4*)(o + c) = v;
    }
}

// ---------------- 64x64 transform: g_h0 = dinv * (relu(g_h1) @ W) ----------------
// block 256 = 32 nodes x 8 channel-groups; W in smem with 10-float chunk stride
// (chunk g at k*80 + g*10 -> LDS.64 across 8 groups hits 8 distinct bank pairs)
__global__ __launch_bounds__(256) void k_transform64(const float* __restrict__ W, int N) {
    __shared__ __align__(16) float sW[64 * 80];   // 20 KB
    __shared__ __align__(16) float sh[32 * 65];   // 8.3 KB
    int tid = threadIdx.x;
    int nodeBase = blockIdx.x * 32;

    #pragma unroll
    for (int i = tid; i < 4096; i += 256) {
        int k = i >> 6, c = i & 63;
        sW[k * 80 + (c >> 3) * 10 + (c & 7)] = W[i];
    }
    for (int i = tid; i < 2048; i += 256) {
        int n = i >> 6, c = i & 63;
        float v = 0.0f;
        if (nodeBase + n < N) v = fmaxf(g_h1[(size_t)(nodeBase + n) * HDIM + c], 0.0f);
        sh[n * 65 + c] = v;
    }
    __syncthreads();

    int n = tid >> 3;       // 0..31
    int g = tid & 7;        // channel group: channels g*8 .. g*8+7
    unsigned long long acc0 = 0ull, acc1 = 0ull, acc2 = 0ull, acc3 = 0ull;
    const float* shrow = &sh[n * 65];
    const float* wch   = &sW[g * 10];
    #pragma unroll
    for (int k = 0; k < 64; k++) {
        float hv = shrow[k];
        unsigned long long hv2 = pack2(hv, hv);
        const float* w = wch + k * 80;
        fma2(acc0, hv2, *(const unsigned long long*)(w + 0));
        fma2(acc1, hv2, *(const unsigned long long*)(w + 2));
        fma2(acc2, hv2, *(const unsigned long long*)(w + 4));
        fma2(acc3, hv2, *(const unsigned long long*)(w + 6));
    }

    int node = nodeBase + n;
    if (node < N) {
        float di = g_dinv[node];
        float2 r0 = unpack2(acc0), r1 = unpack2(acc1);
        float2 r2 = unpack2(acc2), r3 = unpack2(acc3);
        float* o = g_h0 + (size_t)node * HDIM + g * 8;
        *(float4*)o       = make_float4(r0.x * di, r0.y * di, r1.x * di, r1.y * di);
        *((float4*)o + 1) = make_float4(r2.x * di, r2.y * di, r3.x * di, r3.y * di);
    }
}

// ---------------- CSR aggregation: g_h1[d] = b + dinv[d]*(g_h0[d] + sum g_h0[src]) ----------------
// one warp per dst node, 2 channels per lane
__global__ __launch_bounds__(256) void k_agg_csr(const float* __restrict__ b, int N) {
    int warp = (blockIdx.x * blockDim.x + threadIdx.x) >> 5;
    int lane = threadIdx.x & 31;
    if (warp >= N) return;
    int d = warp;
    const float* hd = g_h0 + (size_t)d * HDIM;
    float a0 = hd[lane];
    float a1 = hd[lane + 32];
    int beg = g_rowptr[d], end = g_rowptr[d + 1];
    for (int i = beg; i < end; i++) {
        int s = g_esrc[i];
        const float* hs = g_h0 + (size_t)s * HDIM;
        a0 += hs[lane];
        a1 += hs[lane + 32];
    }
    float di = g_dinv[d];
    float* o = g_h1 + (size_t)d * HDIM;
    o[lane]      = b[lane]      + di * a0;
    o[lane + 32] = b[lane + 32] + di * a1;
}

// ---------------- pooling / final ----------------
__global__ void k_zero_pool() {
    if (threadIdx.x < HDIM) g_pool[threadIdx.x] = 0.0f;
}

__global__ void k_pool(int N) {
    __shared__ float sdata[256];
    int tid = threadIdx.x;
    size_t total = (size_t)N * HDIM;
    size_t stride = (size_t)gridDim.x * blockDim.x;
    float local = 0.0f;
    for (size_t i = (size_t)blockIdx.x * blockDim.x + tid; i < total; i += stride)
        local += fmaxf(g_h1[i], 0.0f);
    sdata[tid] = local;
    __syncthreads();
    if (tid < 64) {
        float s = sdata[tid] + sdata[tid + 64] + sdata[tid + 128] + sdata[tid + 192];
        atomicAdd(&g_pool[tid], s);
    }
}

__global__ void k_final(const float* __restrict__ Wfc, const float* __restrict__ bfc,
                        float* __restrict__ out, int N) {
    int c = threadIdx.x;
    if (c >= 24) return;
    float invN = 1.0f / (float)N;
    float acc = bfc[c];
    #pragma unroll
    for (int k = 0; k < 64; k++)
        acc += (g_pool[k] * invN) * Wfc[k * 24 + c];
    out[c] = tanhf(acc);
}

// ---------------- launch ----------------
extern "C" void kernel_launch(void* const* d_in, const int* in_sizes, int n_in,
                              void* d_out, int out_size) {
    const float* x   = (const float*)d_in[0];
    const int*   ei  = (const int*)d_in[1];   // int32 (JAX x64 disabled)
    const float* W1  = (const float*)d_in[3];
    const float* b1  = (const float*)d_in[4];
    const float* W2  = (const float*)d_in[5];
    const float* b2  = (const float*)d_in[6];
    const float* W3  = (const float*)d_in[7];
    const float* b3  = (const float*)d_in[8];
    const float* Wfc = (const float*)d_in[9];
    const float* bfc = (const float*)d_in[10];
    float* out = (float*)d_out;

    int N = in_sizes[0] / 3;
    int E = in_sizes[1] / 2;

    const int T = 256;
    int nbN   = (N + T - 1) / T;
    int nbE   = (E + T - 1) / T;
    int nbTr  = (N + 31) / 32;
    int nbAgg = (N + 7) / 8;                       // 8 warps per block, warp per node
    int nbScan = (N + SCAN_ITEMS - 1) / SCAN_ITEMS;

    // CSR + normalization
    k_zero<<<nbN, T>>>(N);
    k_hist<<<nbE, T>>>(ei, E);
    k_prep<<<nbN, T>>>(x, N);
    k_scan_local<<<nbScan, SCAN_T>>>(N);
    k_scan_bsums<<<1, SCAN_T>>>(nbScan);
    k_scan_add<<<nbN, T>>>(N, E);
    k_fill<<<nbE, T>>>(ei, E);

    // layer 1 (flipped: aggregate x, then transform)
    k_agg_x<<<nbN, T>>>(N);
    k_l1<<<nbN, T>>>(W1, b1, N);

    // layer 2
    k_transform64<<<nbTr, T>>>(W2, N);
    k_agg_csr<<<nbAgg, T>>>(b2, N);

    // layer 3
    k_transform64<<<nbTr, T>>>(W3, N);
    k_agg_csr<<<nbAgg, T>>>(b3, N);

    // pool + FC + tanh
    k_zero_pool<<<1, 64>>>();
    k_pool<<<2048, T>>>(N);
    k_final<<<1, 32>>>(Wfc, bfc, out, N);
}

// round 4
// speedup vs baseline: 3.3122x; 1.5910x over previous
#include <cuda_runtime.h>
#include <cuda_bf16.h>
#include <math.h>

#define MAX_N 500000
#define MAX_E 1000000
#define HDIM  64
#define SCAN_T 512
#define SCAN_ITEMS 1024
#define POOL_BLOCKS 2960   // grid for fused agg+pool (20 waves of 148)

// ---------------- device scratch ----------------
__device__ float g_h0[(size_t)MAX_N * HDIM];     // scaled messages (dinv * transform out)
__device__ float g_h1[(size_t)MAX_N * HDIM];     // layer output (post-aggregate, pre-relu)
__device__ float g_dinv[MAX_N];
__device__ float g_xs[(size_t)MAX_N * 3];        // dinv-scaled input features
__device__ float g_xa[(size_t)MAX_N * 3];        // aggregated input features
__device__ int   g_degi[MAX_N];
__device__ int   g_rowptr[MAX_N + 1];
__device__ int   g_cursor[MAX_N];
__device__ int   g_esrc[MAX_E];
__device__ int   g_bsum[1024];
__device__ float g_partial[(size_t)POOL_BLOCKS * HDIM];
__device__ float g_pool[HDIM];

// ---------------- f32x2 packed helpers (Blackwell FFMA2) ----------------
__device__ __forceinline__ unsigned long long pack2(float a, float b) {
    unsigned long long r;
    asm("mov.b64 %0, {%1, %2};" : "=l"(r) : "f"(a), "f"(b));
    return r;
}
__device__ __forceinline__ void fma2(unsigned long long& d, unsigned long long a, unsigned long long b) {
    asm("fma.rn.f32x2 %0, %1, %2, %0;" : "+l"(d) : "l"(a), "l"(b));
}
__device__ __forceinline__ float2 unpack2(unsigned long long v) {
    float2 f;
    asm("mov.b64 {%0, %1}, %2;" : "=f"(f.x), "=f"(f.y) : "l"(v));
    return f;
}

// ---------------- degree / prep ----------------
__global__ void k_zero(int N) {
    int i = blockIdx.x * blockDim.x + threadIdx.x;
    if (i < N) { g_degi[i] = 0; g_cursor[i] = 0; }
}

__global__ void k_hist(const int* __restrict__ ei, int E) {
    int e = blockIdx.x * blockDim.x + threadIdx.x;
    if (e < E) atomicAdd(&g_degi[ei[E + e]], 1);
}

__global__ void k_prep(const float* __restrict__ x, int N) {
    int i = blockIdx.x * blockDim.x + threadIdx.x;
    if (i >= N) return;
    float di = rsqrtf((float)(g_degi[i] + 1));
    g_dinv[i] = di;
    g_xs[(size_t)i * 3 + 0] = di * x[(size_t)i * 3 + 0];
    g_xs[(size_t)i * 3 + 1] = di * x[(size_t)i * 3 + 1];
    g_xs[(size_t)i * 3 + 2] = di * x[(size_t)i * 3 + 2];
}

// ---------------- exclusive scan of g_degi -> g_rowptr ----------------
__global__ __launch_bounds__(SCAN_T) void k_scan_local(int N) {
    __shared__ int sdata[SCAN_T];
    int base = blockIdx.x * SCAN_ITEMS;
    int i0 = base + threadIdx.x * 2;
    int d0 = (i0     < N) ? g_degi[i0]     : 0;
    int d1 = (i0 + 1 < N) ? g_degi[i0 + 1] : 0;
    int tsum = d0 + d1;
    sdata[threadIdx.x] = tsum;
    __syncthreads();
    for (int off = 1; off < SCAN_T; off <<= 1) {
        int v = (threadIdx.x >= off) ? sdata[threadIdx.x - off] : 0;
        __syncthreads();
        sdata[threadIdx.x] += v;
        __syncthreads();
    }
    int excl = sdata[threadIdx.x] - tsum;
    if (i0     < N) g_rowptr[i0]     = excl;
    if (i0 + 1 < N) g_rowptr[i0 + 1] = excl + d0;
    if (threadIdx.x == SCAN_T - 1) g_bsum[blockIdx.x] = sdata[SCAN_T - 1];
}

__global__ __launch_bounds__(SCAN_T) void k_scan_bsums(int B) {
    __shared__ int sdata[SCAN_T];
    int v = (threadIdx.x < B) ? g_bsum[threadIdx.x] : 0;
    sdata[threadIdx.x] = v;
    __syncthreads();
    for (int off = 1; off < SCAN_T; off <<= 1) {
        int p = (threadIdx.x >= off) ? sdata[threadIdx.x - off] : 0;
        __syncthreads();
        sdata[threadIdx.x] += p;
        __syncthreads();
    }
    if (threadIdx.x < B) g_bsum[threadIdx.x] = sdata[threadIdx.x] - v;
}

__global__ void k_scan_add(int N, int E) {
    int i = blockIdx.x * blockDim.x + threadIdx.x;
    if (i < N) g_rowptr[i] += g_bsum[i / SCAN_ITEMS];
    if (i == 0) g_rowptr[N] = E;
}

__global__ void k_fill(const int* __restrict__ ei, int E) {
    int e = blockIdx.x * blockDim.x + threadIdx.x;
    if (e >= E) return;
    int s = ei[e];
    int d = ei[E + e];
    int pos = g_rowptr[d] + atomicAdd(&g_cursor[d], 1);
    g_esrc[pos] = s;
}

// ---------------- layer 1: aggregate x (3-wide), then h1 = xa @ W1 + b1 ----------------
__global__ void k_agg_x(int N) {
    int d = blockIdx.x * blockDim.x + threadIdx.x;
    if (d >= N) return;
    float a0 = g_xs[(size_t)d * 3 + 0];
    float a1 = g_xs[(size_t)d * 3 + 1];
    float a2 = g_xs[(size_t)d * 3 + 2];
    int beg = g_rowptr[d], end = g_rowptr[d + 1];
    for (int i = beg; i < end; i++) {
        int s = g_esrc[i];
        a0 += g_xs[(size_t)s * 3 + 0];
        a1 += g_xs[(size_t)s * 3 + 1];
        a2 += g_xs[(size_t)s * 3 + 2];
    }
    float di = g_dinv[d];
    g_xa[(size_t)d * 3 + 0] = di * a0;
    g_xa[(size_t)d * 3 + 1] = di * a1;
    g_xa[(size_t)d * 3 + 2] = di * a2;
}

__global__ __launch_bounds__(256) void k_l1(const float* __restrict__ W1,
                                            const float* __restrict__ b1, int N) {
    __shared__ float sW[3 * 64];
    __shared__ float sb[64];
    int tid = threadIdx.x;
    if (tid < 192) sW[tid] = W1[tid];
    if (tid < 64)  sb[tid] = b1[tid];
    __syncthreads();
    int n = blockIdx.x * blockDim.x + tid;
    if (n >= N) return;
    float x0 = g_xa[(size_t)n * 3 + 0];
    float x1 = g_xa[(size_t)n * 3 + 1];
    float x2 = g_xa[(size_t)n * 3 + 2];
    float* o = g_h1 + (size_t)n * HDIM;
    #pragma unroll
    for (int c = 0; c < 64; c += 4) {
        float4 v;
        v.x = sb[c+0] + x0 * sW[c+0] + x1 * sW[64+c+0] + x2 * sW[128+c+0];
        v.y = sb[c+1] + x0 * sW[c+1] + x1 * sW[64+c+1] + x2 * sW[128+c+1];
        v.z = sb[c+2] + x0 * sW[c+2] + x1 * sW[64+c+2] + x2 * sW[128+c+2];
        v.w = sb[c+3] + x0 * sW[c+3] + x1 * sW[64+c+3] + x2 * sW[128+c+3];
        *(float4*)(o + c) = v;
    }
}

// ---------------- 64x64 transform: g_h0 = dinv * (relu(g_h1) @ W) ----------------
// 64 nodes/block, 256 threads; thread (m=tid>>3, g=tid&7) computes nodes {m, m+32},
// channels g*8..g*8+7. 8 FFMA2 per 6 LDS per k-step -> FMA-pipe bound.
__global__ __launch_bounds__(256) void k_transform64(const float* __restrict__ W, int N) {
    __shared__ __align__(16) float sW[64 * 80];   // 20.5 KB, 10-float channel-group stride
    __shared__ __align__(16) float sh[64 * 65];   // 16.6 KB, padded rows
    int tid = threadIdx.x;
    int nodeBase = blockIdx.x * 64;

    #pragma unroll
    for (int i = tid; i < 4096; i += 256) {
        int k = i >> 6, c = i & 63;
        sW[k * 80 + (c >> 3) * 10 + (c & 7)] = W[i];
    }
    #pragma unroll
    for (int i = tid; i < 4096; i += 256) {
        int n = i >> 6, c = i & 63;
        float v = 0.0f;
        if (nodeBase + n < N) v = fmaxf(g_h1[(size_t)(nodeBase + n) * HDIM + c], 0.0f);
        sh[n * 65 + c] = v;
    }
    __syncthreads();

    int m = tid >> 3;       // 0..31
    int g = tid & 7;
    unsigned long long a0 = 0ull, a1 = 0ull, a2 = 0ull, a3 = 0ull;  // node m
    unsigned long long b0 = 0ull, b1 = 0ull, b2 = 0ull, b3 = 0ull;  // node m+32
    const float* r0 = &sh[m * 65];
    const float* r1 = &sh[(m + 32) * 65];
    const float* wch = &sW[g * 10];
    #pragma unroll
    for (int k = 0; k < 64; k++) {
        float h0v = r0[k];
        float h1v = r1[k];
        unsigned long long h0 = pack2(h0v, h0v);
        unsigned long long h1 = pack2(h1v, h1v);
        const unsigned long long* w = (const unsigned long long*)(wch + k * 80);
        fma2(a0, h0, w[0]); fma2(a1, h0, w[1]); fma2(a2, h0, w[2]); fma2(a3, h0, w[3]);
        fma2(b0, h1, w[0]); fma2(b1, h1, w[1]); fma2(b2, h1, w[2]); fma2(b3, h1, w[3]);
    }

    int n0 = nodeBase + m;
    int n1 = nodeBase + m + 32;
    if (n0 < N) {
        float di = g_dinv[n0];
        float2 r00 = unpack2(a0), r01 = unpack2(a1), r02 = unpack2(a2), r03 = unpack2(a3);
        float* o = g_h0 + (size_t)n0 * HDIM + g * 8;
        *(float4*)o       = make_float4(r00.x * di, r00.y * di, r01.x * di, r01.y * di);
        *((float4*)o + 1) = make_float4(r02.x * di, r02.y * di, r03.x * di, r03.y * di);
    }
    if (n1 < N) {
        float di = g_dinv[n1];
        float2 r10 = unpack2(b0), r11 = unpack2(b1), r12 = unpack2(b2), r13 = unpack2(b3);
        float* o = g_h0 + (size_t)n1 * HDIM + g * 8;
        *(float4*)o       = make_float4(r10.x * di, r10.y * di, r11.x * di, r11.y * di);
        *((float4*)o + 1) = make_float4(r12.x * di, r12.y * di, r13.x * di, r13.y * di);
    }
}

// ---------------- CSR aggregation (layer 2): half-warp per dst node, float4 lanes ----------------
__global__ __launch_bounds__(256) void k_agg_csr(const float* __restrict__ b, int N) {
    int warp = (blockIdx.x * blockDim.x + threadIdx.x) >> 5;
    int lane = threadIdx.x & 31;
    int half = lane >> 4;
    int l16  = lane & 15;
    int d = warp * 2 + half;
    if (d >= N) return;
    const float4* hd = (const float4*)(g_h0 + (size_t)d * HDIM);
    float4 a = hd[l16];
    int beg = g_rowptr[d], end = g_rowptr[d + 1];
    for (int i = beg; i < end; i++) {
        int s = g_esrc[i];
        float4 v = ((const float4*)(g_h0 + (size_t)s * HDIM))[l16];
        a.x += v.x; a.y += v.y; a.z += v.z; a.w += v.w;
    }
    float di = g_dinv[d];
    float4 bb = ((const float4*)b)[l16];
    float4* o = (float4*)(g_h1 + (size_t)d * HDIM);
    o[l16] = make_float4(bb.x + di * a.x, bb.y + di * a.y,
                         bb.z + di * a.z, bb.w + di * a.w);
}

// ---------------- fused layer-3 aggregation + relu + pool partials ----------------
// grid-stride, 16 nodes per block-iteration; per-thread channel accumulators.
__global__ __launch_bounds__(256) void k_agg_pool(const float* __restrict__ b, int N) {
    int tid  = threadIdx.x;
    int warpInBlk = tid >> 5;
    int lane = tid & 31;
    int half = lane >> 4;
    int l16  = lane & 15;
    float4 bb = ((const float4*)b)[l16];
    float4 acc = make_float4(0.f, 0.f, 0.f, 0.f);

    int stride = gridDim.x * 16;
    for (int d = blockIdx.x * 16 + warpInBlk * 2 + half; d < N; d += stride) {
        const float4* hd = (const float4*)(g_h0 + (size_t)d * HDIM);
        float4 a = hd[l16];
        int beg = g_rowptr[d], end = g_rowptr[d + 1];
        for (int i = beg; i < end; i++) {
            int s = g_esrc[i];
            float4 v = ((const float4*)(g_h0 + (size_t)s * HDIM))[l16];
            a.x += v.x; a.y += v.y; a.z += v.z; a.w += v.w;
        }
        float di = g_dinv[d];
        acc.x += fmaxf(bb.x + di * a.x, 0.f);
        acc.y += fmaxf(bb.y + di * a.y, 0.f);
        acc.z += fmaxf(bb.z + di * a.z, 0.f);
        acc.w += fmaxf(bb.w + di * a.w, 0.f);
    }

    __shared__ float sp[64];
    if (tid < 64) sp[tid] = 0.0f;
    __syncthreads();
    atomicAdd(&sp[l16 * 4 + 0], acc.x);
    atomicAdd(&sp[l16 * 4 + 1], acc.y);
    atomicAdd(&sp[l16 * 4 + 2], acc.z);
    atomicAdd(&sp[l16 * 4 + 3], acc.w);
    __syncthreads();
    if (tid < 64) g_partial[(size_t)blockIdx.x * HDIM + tid] = sp[tid];
}

// reduce partials: 64 blocks, block c sums channel c over POOL_BLOCKS rows
__global__ __launch_bounds__(256) void k_reduce(int numPartial) {
    __shared__ float sdata[256];
    int c = blockIdx.x;
    float s = 0.0f;
    for (int i = threadIdx.x; i < numPartial; i += 256)
        s += g_partial[(size_t)i * HDIM + c];
    sdata[threadIdx.x] = s;
    __syncthreads();
    for (int off = 128; off > 0; off >>= 1) {
        if (threadIdx.x < off) sdata[threadIdx.x] += sdata[threadIdx.x + off];
        __syncthreads();
    }
    if (threadIdx.x == 0) g_pool[c] = sdata[0];
}

__global__ void k_final(const float* __restrict__ Wfc, const float* __restrict__ bfc,
                        float* __restrict__ out, int N) {
    int c = threadIdx.x;
    if (c >= 24) return;
    float invN = 1.0f / (float)N;
    float acc = bfc[c];
    #pragma unroll
    for (int k = 0; k < 64; k++)
        acc += (g_pool[k] * invN) * Wfc[k * 24 + c];
    out[c] = tanhf(acc);
}

// ---------------- launch ----------------
extern "C" void kernel_launch(void* const* d_in, const int* in_sizes, int n_in,
                              void* d_out, int out_size) {
    const float* x   = (const float*)d_in[0];
    const int*   ei  = (const int*)d_in[1];   // int32 (JAX x64 disabled)
    const float* W1  = (const float*)d_in[3];
    const float* b1  = (const float*)d_in[4];
    const float* W2  = (const float*)d_in[5];
    const float* b2  = (const float*)d_in[6];
    const float* W3  = (const float*)d_in[7];
    const float* b3  = (const float*)d_in[8];
    const float* Wfc = (const float*)d_in[9];
    const float* bfc = (const float*)d_in[10];
    float* out = (float*)d_out;

    int N = in_sizes[0] / 3;
    int E = in_sizes[1] / 2;

    const int T = 256;
    int nbN    = (N + T - 1) / T;
    int nbE    = (E + T - 1) / T;
    int nbTr   = (N + 63) / 64;
    int nbAgg  = (N + 15) / 16;                  // 16 nodes per 256-thread block
    int nbScan = (N + SCAN_ITEMS - 1) / SCAN_ITEMS;

    // CSR + normalization
    k_zero<<<nbN, T>>>(N);
    k_hist<<<nbE, T>>>(ei, E);
    k_prep<<<nbN, T>>>(x, N);
    k_scan_local<<<nbScan, SCAN_T>>>(N);
    k_scan_bsums<<<1, SCAN_T>>>(nbScan);
    k_scan_add<<<nbN, T>>>(N, E);
    k_fill<<<nbE, T>>>(ei, E);

    // layer 1 (flipped: aggregate x, then transform)
    k_agg_x<<<nbN, T>>>(N);
    k_l1<<<nbN, T>>>(W1, b1, N);

    // layer 2
    k_transform64<<<nbTr, T>>>(W2, N);
    k_agg_csr<<<nbAgg, T>>>(b2, N);

    // layer 3 (aggregation fused with relu + mean-pool partials)
    k_transform64<<<nbTr, T>>>(W3, N);
    k_agg_pool<<<POOL_BLOCKS, T>>>(b3, N);

    // reduce + FC + tanh
    k_reduce<<<64, 256>>>(POOL_BLOCKS);
    k_final<<<1, 32>>>(Wfc, bfc, out, N);
}

// round 5
// speedup vs baseline: 4.0149x; 1.2122x over previous
#include <cuda_runtime.h>
#include <cuda_bf16.h>
#include <math.h>

#define MAX_N 500000
#define MAX_E 1000000
#define HDIM  64
#define SCAN_T 512
#define SCAN_ITEMS 1024
#define POOL_BLOCKS 2960

// ---------------- device scratch ----------------
__device__ float g_h0[(size_t)MAX_N * HDIM];     // layer-2 messages: dinv*(relu(h1)@W2)
__device__ float g_h1[(size_t)MAX_N * HDIM];     // layer-3 messages: dinv*(relu(agg2)@W3)
__device__ float g_dinv[MAX_N];
__device__ float g_xs[(size_t)MAX_N * 3];        // dinv-scaled input features
__device__ float g_xa[(size_t)MAX_N * 3];        // aggregated input features
__device__ int   g_degi[MAX_N];
__device__ int   g_rowptr[MAX_N + 1];
__device__ int   g_cursor[MAX_N];
__device__ int   g_esrc[MAX_E];
__device__ int   g_bsum[1024];
__device__ float g_partial[(size_t)POOL_BLOCKS * HDIM];
__device__ float g_pool[HDIM];

// ---------------- f32x2 packed helpers (Blackwell FFMA2) ----------------
__device__ __forceinline__ unsigned long long pack2(float a, float b) {
    unsigned long long r;
    asm("mov.b64 %0, {%1, %2};" : "=l"(r) : "f"(a), "f"(b));
    return r;
}
__device__ __forceinline__ void fma2(unsigned long long& d, unsigned long long a, unsigned long long b) {
    asm("fma.rn.f32x2 %0, %1, %2, %0;" : "+l"(d) : "l"(a), "l"(b));
}
__device__ __forceinline__ float2 unpack2(unsigned long long v) {
    float2 f;
    asm("mov.b64 {%0, %1}, %2;" : "=f"(f.x), "=f"(f.y) : "l"(v));
    return f;
}

// ---------------- degree / prep / CSR ----------------
__global__ void k_zero(int N) {
    int i = blockIdx.x * blockDim.x + threadIdx.x;
    if (i < N) { g_degi[i] = 0; g_cursor[i] = 0; }
}

__global__ void k_hist(const int* __restrict__ ei, int E) {
    int e = blockIdx.x * blockDim.x + threadIdx.x;
    if (e < E) atomicAdd(&g_degi[ei[E + e]], 1);
}

__global__ void k_prep(const float* __restrict__ x, int N) {
    int i = blockIdx.x * blockDim.x + threadIdx.x;
    if (i >= N) return;
    float di = rsqrtf((float)(g_degi[i] + 1));
    g_dinv[i] = di;
    g_xs[(size_t)i * 3 + 0] = di * x[(size_t)i * 3 + 0];
    g_xs[(size_t)i * 3 + 1] = di * x[(size_t)i * 3 + 1];
    g_xs[(size_t)i * 3 + 2] = di * x[(size_t)i * 3 + 2];
}

__global__ __launch_bounds__(SCAN_T) void k_scan_local(int N) {
    __shared__ int sdata[SCAN_T];
    int base = blockIdx.x * SCAN_ITEMS;
    int i0 = base + threadIdx.x * 2;
    int d0 = (i0     < N) ? g_degi[i0]     : 0;
    int d1 = (i0 + 1 < N) ? g_degi[i0 + 1] : 0;
    int tsum = d0 + d1;
    sdata[threadIdx.x] = tsum;
    __syncthreads();
    for (int off = 1; off < SCAN_T; off <<= 1) {
        int v = (threadIdx.x >= off) ? sdata[threadIdx.x - off] : 0;
        __syncthreads();
        sdata[threadIdx.x] += v;
        __syncthreads();
    }
    int excl = sdata[threadIdx.x] - tsum;
    if (i0     < N) g_rowptr[i0]     = excl;
    if (i0 + 1 < N) g_rowptr[i0 + 1] = excl + d0;
    if (threadIdx.x == SCAN_T - 1) g_bsum[blockIdx.x] = sdata[SCAN_T - 1];
}

__global__ __launch_bounds__(SCAN_T) void k_scan_bsums(int B) {
    __shared__ int sdata[SCAN_T];
    int v = (threadIdx.x < B) ? g_bsum[threadIdx.x] : 0;
    sdata[threadIdx.x] = v;
    __syncthreads();
    for (int off = 1; off < SCAN_T; off <<= 1) {
        int p = (threadIdx.x >= off) ? sdata[threadIdx.x - off] : 0;
        __syncthreads();
        sdata[threadIdx.x] += p;
        __syncthreads();
    }
    if (threadIdx.x < B) g_bsum[threadIdx.x] = sdata[threadIdx.x] - v;
}

__global__ void k_scan_add(int N, int E) {
    int i = blockIdx.x * blockDim.x + threadIdx.x;
    if (i < N) g_rowptr[i] += g_bsum[i / SCAN_ITEMS];
    if (i == 0) g_rowptr[N] = E;
}

__global__ void k_fill(const int* __restrict__ ei, int E) {
    int e = blockIdx.x * blockDim.x + threadIdx.x;
    if (e >= E) return;
    int s = ei[e];
    int d = ei[E + e];
    int pos = g_rowptr[d] + atomicAdd(&g_cursor[d], 1);
    g_esrc[pos] = s;
}

// ---------------- layer 1 input aggregation (3-wide) ----------------
__global__ void k_agg_x(int N) {
    int d = blockIdx.x * blockDim.x + threadIdx.x;
    if (d >= N) return;
    float a0 = g_xs[(size_t)d * 3 + 0];
    float a1 = g_xs[(size_t)d * 3 + 1];
    float a2 = g_xs[(size_t)d * 3 + 2];
    int beg = g_rowptr[d], end = g_rowptr[d + 1];
    for (int i = beg; i < end; i++) {
        int s = g_esrc[i];
        a0 += g_xs[(size_t)s * 3 + 0];
        a1 += g_xs[(size_t)s * 3 + 1];
        a2 += g_xs[(size_t)s * 3 + 2];
    }
    float di = g_dinv[d];
    g_xa[(size_t)d * 3 + 0] = di * a0;
    g_xa[(size_t)d * 3 + 1] = di * a1;
    g_xa[(size_t)d * 3 + 2] = di * a2;
}

// ---------------- shared GEMM phase: sh(relu'd inputs) @ sW -> out buffer ----------------
// sh stride 68 floats; sW stride 80 with 10-float channel groups.
__device__ __forceinline__ void gemm_phase(const float* sh, const float* sW,
                                           float* outBuf, int nodeBase, int N) {
    int tid = threadIdx.x;
    int m = tid >> 3;       // 0..31
    int g = tid & 7;
    unsigned long long a0 = 0ull, a1 = 0ull, a2 = 0ull, a3 = 0ull;
    unsigned long long b0 = 0ull, b1 = 0ull, b2 = 0ull, b3 = 0ull;
    const float* r0 = &sh[m * 68];
    const float* r1 = &sh[(m + 32) * 68];
    const float* wch = &sW[g * 10];
    #pragma unroll
    for (int k = 0; k < 64; k++) {
        float h0v = r0[k];
        float h1v = r1[k];
        unsigned long long h0 = pack2(h0v, h0v);
        unsigned long long h1 = pack2(h1v, h1v);
        const unsigned long long* w = (const unsigned long long*)(wch + k * 80);
        fma2(a0, h0, w[0]); fma2(a1, h0, w[1]); fma2(a2, h0, w[2]); fma2(a3, h0, w[3]);
        fma2(b0, h1, w[0]); fma2(b1, h1, w[1]); fma2(b2, h1, w[2]); fma2(b3, h1, w[3]);
    }

    int n0 = nodeBase + m;
    int n1 = nodeBase + m + 32;
    if (n0 < N) {
        float di = g_dinv[n0];
        float2 r00 = unpack2(a0), r01 = unpack2(a1), r02 = unpack2(a2), r03 = unpack2(a3);
        float* o = outBuf + (size_t)n0 * HDIM + g * 8;
        *(float4*)o       = make_float4(r00.x * di, r00.y * di, r01.x * di, r01.y * di);
        *((float4*)o + 1) = make_float4(r02.x * di, r02.y * di, r03.x * di, r03.y * di);
    }
    if (n1 < N) {
        float di = g_dinv[n1];
        float2 r10 = unpack2(b0), r11 = unpack2(b1), r12 = unpack2(b2), r13 = unpack2(b3);
        float* o = outBuf + (size_t)n1 * HDIM + g * 8;
        *(float4*)o       = make_float4(r10.x * di, r10.y * di, r11.x * di, r11.y * di);
        *((float4*)o + 1) = make_float4(r12.x * di, r12.y * di, r13.x * di, r13.y * di);
    }
}

// ---------------- kA: fused layer-1 transform + layer-2 transform ----------------
// sh = relu(xa @ W1 + b1); g_h0 = dinv * (sh @ W2)
__global__ __launch_bounds__(256) void kA_l12(const float* __restrict__ W1,
                                              const float* __restrict__ b1,
                                              const float* __restrict__ W2, int N) {
    __shared__ __align__(16) float sW[64 * 80];   // W2, 20.5 KB
    __shared__ __align__(16) float sh[64 * 68];   // 17.4 KB
    __shared__ float sW1[192];
    __shared__ float sb1[64];
    __shared__ float sxa[192];
    int tid = threadIdx.x;
    int nodeBase = blockIdx.x * 64;

    if (tid < 192) {
        sW1[tid] = W1[tid];
        int n = nodeBase + tid / 3;
        sxa[tid] = (n < N) ? g_xa[(size_t)nodeBase * 3 + tid] : 0.0f;
    }
    if (tid < 64) sb1[tid] = b1[tid];
    #pragma unroll
    for (int i = tid; i < 4096; i += 256) {
        int k = i >> 6, c = i & 63;
        sW[k * 80 + (c >> 3) * 10 + (c & 7)] = W2[i];
    }
    __syncthreads();

    #pragma unroll
    for (int i = tid; i < 4096; i += 256) {
        int n = i >> 6, c = i & 63;
        float v = sb1[c] + sxa[n * 3] * sW1[c] + sxa[n * 3 + 1] * sW1[64 + c]
                         + sxa[n * 3 + 2] * sW1[128 + c];
        sh[n * 68 + c] = fmaxf(v, 0.0f);
    }
    __syncthreads();

    gemm_phase(sh, sW, g_h0, nodeBase, N);
}

// ---------------- kB: fused layer-2 aggregation + layer-3 transform ----------------
// sh = relu(b2 + dinv*(h0[d] + sum h0[src])); g_h1 = dinv * (sh @ W3)
__global__ __launch_bounds__(256) void kB_agg_tr(const float* __restrict__ b2,
                                                 const float* __restrict__ W3, int N) {
    __shared__ __align__(16) float sW[64 * 80];
    __shared__ __align__(16) float sh[64 * 68];
    __shared__ float sb2[64];
    int tid = threadIdx.x;
    int nodeBase = blockIdx.x * 64;

    if (tid < 64) sb2[tid] = b2[tid];
    #pragma unroll
    for (int i = tid; i < 4096; i += 256) {
        int k = i >> 6, c = i & 63;
        sW[k * 80 + (c >> 3) * 10 + (c & 7)] = W3[i];
    }

    // aggregation phase: 8 warps x 8 nodes each; half-warp float4 per node
    {
        int w    = tid >> 5;
        int lane = tid & 31;
        int half = lane >> 4;
        int l16  = lane & 15;
        #pragma unroll
        for (int j = 0; j < 4; j++) {
            int nl = w * 8 + j * 2 + half;       // local node 0..63
            int d  = nodeBase + nl;
            float4 a = make_float4(0.f, 0.f, 0.f, 0.f);
            float di = 0.0f;
            if (d < N) {
                a = ((const float4*)(g_h0 + (size_t)d * HDIM))[l16];
                int beg = g_rowptr[d], end = g_rowptr[d + 1];
                for (int i = beg; i < end; i++) {
                    int s = g_esrc[i];
                    float4 v = ((const float4*)(g_h0 + (size_t)s * HDIM))[l16];
                    a.x += v.x; a.y += v.y; a.z += v.z; a.w += v.w;
                }
                di = g_dinv[d];
            }
            float4 bb = ((const float4*)sb2)[l16];
            float4 r;
            r.x = fmaxf(bb.x + di * a.x, 0.f);
            r.y = fmaxf(bb.y + di * a.y, 0.f);
            r.z = fmaxf(bb.z + di * a.z, 0.f);
            r.w = fmaxf(bb.w + di * a.w, 0.f);
            *(float4*)&sh[nl * 68 + l16 * 4] = r;
        }
    }
    __syncthreads();

    gemm_phase(sh, sW, g_h1, nodeBase, N);
}

// ---------------- kC: fused layer-3 aggregation + relu + pool partials ----------------
__global__ __launch_bounds__(256) void kC_agg_pool(const float* __restrict__ b, int N) {
    int tid  = threadIdx.x;
    int warpInBlk = tid >> 5;
    int lane = tid & 31;
    int half = lane >> 4;
    int l16  = lane & 15;
    float4 bb = ((const float4*)b)[l16];
    float4 acc = make_float4(0.f, 0.f, 0.f, 0.f);

    int stride = gridDim.x * 16;
    for (int d = blockIdx.x * 16 + warpInBlk * 2 + half; d < N; d += stride) {
        const float4* hd = (const float4*)(g_h1 + (size_t)d * HDIM);
        float4 a = hd[l16];
        int beg = g_rowptr[d], end = g_rowptr[d + 1];
        for (int i = beg; i < end; i++) {
            int s = g_esrc[i];
            float4 v = ((const float4*)(g_h1 + (size_t)s * HDIM))[l16];
            a.x += v.x; a.y += v.y; a.z += v.z; a.w += v.w;
        }
        float di = g_dinv[d];
        acc.x += fmaxf(bb.x + di * a.x, 0.f);
        acc.y += fmaxf(bb.y + di * a.y, 0.f);
        acc.z += fmaxf(bb.z + di * a.z, 0.f);
        acc.w += fmaxf(bb.w + di * a.w, 0.f);
    }

    __shared__ float sp[64];
    if (tid < 64) sp[tid] = 0.0f;
    __syncthreads();
    atomicAdd(&sp[l16 * 4 + 0], acc.x);
    atomicAdd(&sp[l16 * 4 + 1], acc.y);
    atomicAdd(&sp[l16 * 4 + 2], acc.z);
    atomicAdd(&sp[l16 * 4 + 3], acc.w);
    __syncthreads();
    if (tid < 64) g_partial[(size_t)blockIdx.x * HDIM + tid] = sp[tid];
}

__global__ __launch_bounds__(256) void k_reduce(int numPartial) {
    __shared__ float sdata[256];
    int c = blockIdx.x;
    float s = 0.0f;
    for (int i = threadIdx.x; i < numPartial; i += 256)
        s += g_partial[(size_t)i * HDIM + c];
    sdata[threadIdx.x] = s;
    __syncthreads();
    for (int off = 128; off > 0; off >>= 1) {
        if (threadIdx.x < off) sdata[threadIdx.x] += sdata[threadIdx.x + off];
        __syncthreads();
    }
    if (threadIdx.x == 0) g_pool[c] = sdata[0];
}

__global__ void k_final(const float* __restrict__ Wfc, const float* __restrict__ bfc,
                        float* __restrict__ out, int N) {
    int c = threadIdx.x;
    if (c >= 24) return;
    float invN = 1.0f / (float)N;
    float acc = bfc[c];
    #pragma unroll
    for (int k = 0; k < 64; k++)
        acc += (g_pool[k] * invN) * Wfc[k * 24 + c];
    out[c] = tanhf(acc);
}

// ---------------- launch ----------------
extern "C" void kernel_launch(void* const* d_in, const int* in_sizes, int n_in,
                              void* d_out, int out_size) {
    const float* x   = (const float*)d_in[0];
    const int*   ei  = (const int*)d_in[1];   // int32 (JAX x64 disabled)
    const float* W1  = (const float*)d_in[3];
    const float* b1  = (const float*)d_in[4];
    const float* W2  = (const float*)d_in[5];
    const float* b2  = (const float*)d_in[6];
    const float* W3  = (const float*)d_in[7];
    const float* b3  = (const float*)d_in[8];
    const float* Wfc = (const float*)d_in[9];
    const float* bfc = (const float*)d_in[10];
    float* out = (float*)d_out;

    int N = in_sizes[0] / 3;
    int E = in_sizes[1] / 2;

    const int T = 256;
    int nbN    = (N + T - 1) / T;
    int nbE    = (E + T - 1) / T;
    int nbTr   = (N + 63) / 64;
    int nbScan = (N + SCAN_ITEMS - 1) / SCAN_ITEMS;

    // CSR + normalization
    k_zero<<<nbN, T>>>(N);
    k_hist<<<nbE, T>>>(ei, E);
    k_prep<<<nbN, T>>>(x, N);
    k_scan_local<<<nbScan, SCAN_T>>>(N);
    k_scan_bsums<<<1, SCAN_T>>>(nbScan);
    k_scan_add<<<nbN, T>>>(N, E);
    k_fill<<<nbE, T>>>(ei, E);

    // layer 1 aggregation (3-wide)
    k_agg_x<<<nbN, T>>>(N);

    // fused layer1+layer2 transforms -> h0 messages
    kA_l12<<<nbTr, T>>>(W1, b1, W2, N);

    // fused layer2 aggregation + layer3 transform -> h1 messages
    kB_agg_tr<<<nbTr, T>>>(b2, W3, N);

    // fused layer3 aggregation + relu + mean-pool
    kC_agg_pool<<<POOL_BLOCKS, T>>>(b3, N);

    // reduce + FC + tanh
    k_reduce<<<64, 256>>>(POOL_BLOCKS);
    k_final<<<1, 32>>>(Wfc, bfc, out, N);
}

// round 6
// speedup vs baseline: 4.3208x; 1.0762x over previous
#include <cuda_runtime.h>
#include <cuda_bf16.h>
#include <math.h>

#define MAX_N 500000
#define MAX_E 1000000
#define HDIM  64
#define SCAN_T 512
#define SCAN_ITEMS 1024
#define POOL_BLOCKS 2960

// ---------------- device scratch ----------------
__device__ __nv_bfloat16 g_m0[(size_t)MAX_N * HDIM];  // layer-2 messages (bf16, 64 MB -> L2-resident)
__device__ __nv_bfloat16 g_m1[(size_t)MAX_N * HDIM];  // layer-3 messages (bf16)
__device__ float g_dinv[MAX_N];
__device__ float g_xs[(size_t)MAX_N * 3];
__device__ float g_xa[(size_t)MAX_N * 3];
__device__ int   g_degi[MAX_N];
__device__ int   g_rowptr[MAX_N + 1];
__device__ int   g_cursor[MAX_N];
__device__ int   g_esrc[MAX_E];
__device__ int   g_bsum[1024];
__device__ float g_partial[(size_t)POOL_BLOCKS * HDIM];
__device__ float g_pool[HDIM];

// ---------------- packed helpers ----------------
__device__ __forceinline__ unsigned long long pack2(float a, float b) {
    unsigned long long r;
    asm("mov.b64 %0, {%1, %2};" : "=l"(r) : "f"(a), "f"(b));
    return r;
}
__device__ __forceinline__ void fma2(unsigned long long& d, unsigned long long a, unsigned long long b) {
    asm("fma.rn.f32x2 %0, %1, %2, %0;" : "+l"(d) : "l"(a), "l"(b));
}
__device__ __forceinline__ float2 unpack2(unsigned long long v) {
    float2 f;
    asm("mov.b64 {%0, %1}, %2;" : "=f"(f.x), "=f"(f.y) : "l"(v));
    return f;
}
// pack (lo, hi) floats -> bf16x2 word
__device__ __forceinline__ unsigned pack_bf16x2(float lo, float hi) {
    unsigned r;
    asm("cvt.rn.bf16x2.f32 %0, %1, %2;" : "=r"(r) : "f"(hi), "f"(lo));
    return r;
}
// accumulate a bf16x2 word into 2 fp32 accumulators
__device__ __forceinline__ void acc_bf16x2(float& a0, float& a1, unsigned v) {
    __nv_bfloat162 b = *reinterpret_cast<__nv_bfloat162*>(&v);
    float2 f = __bfloat1622float2(b);
    a0 += f.x; a1 += f.y;
}

// ---------------- degree / prep / CSR ----------------
__global__ void k_zero(int N) {
    int i = blockIdx.x * blockDim.x + threadIdx.x;
    if (i < N) { g_degi[i] = 0; g_cursor[i] = 0; }
}

__global__ void k_hist(const int* __restrict__ ei, int E) {
    int e = blockIdx.x * blockDim.x + threadIdx.x;
    if (e < E) atomicAdd(&g_degi[ei[E + e]], 1);
}

__global__ void k_prep(const float* __restrict__ x, int N) {
    int i = blockIdx.x * blockDim.x + threadIdx.x;
    if (i >= N) return;
    float di = rsqrtf((float)(g_degi[i] + 1));
    g_dinv[i] = di;
    g_xs[(size_t)i * 3 + 0] = di * x[(size_t)i * 3 + 0];
    g_xs[(size_t)i * 3 + 1] = di * x[(size_t)i * 3 + 1];
    g_xs[(size_t)i * 3 + 2] = di * x[(size_t)i * 3 + 2];
}

__global__ __launch_bounds__(SCAN_T) void k_scan_local(int N) {
    __shared__ int sdata[SCAN_T];
    int base = blockIdx.x * SCAN_ITEMS;
    int i0 = base + threadIdx.x * 2;
    int d0 = (i0     < N) ? g_degi[i0]     : 0;
    int d1 = (i0 + 1 < N) ? g_degi[i0 + 1] : 0;
    int tsum = d0 + d1;
    sdata[threadIdx.x] = tsum;
    __syncthreads();
    for (int off = 1; off < SCAN_T; off <<= 1) {
        int v = (threadIdx.x >= off) ? sdata[threadIdx.x - off] : 0;
        __syncthreads();
        sdata[threadIdx.x] += v;
        __syncthreads();
    }
    int excl = sdata[threadIdx.x] - tsum;
    if (i0     < N) g_rowptr[i0]     = excl;
    if (i0 + 1 < N) g_rowptr[i0 + 1] = excl + d0;
    if (threadIdx.x == SCAN_T - 1) g_bsum[blockIdx.x] = sdata[SCAN_T - 1];
}

__global__ __launch_bounds__(SCAN_T) void k_scan_bsums(int B) {
    __shared__ int sdata[SCAN_T];
    int v = (threadIdx.x < B) ? g_bsum[threadIdx.x] : 0;
    sdata[threadIdx.x] = v;
    __syncthreads();
    for (int off = 1; off < SCAN_T; off <<= 1) {
        int p = (threadIdx.x >= off) ? sdata[threadIdx.x - off] : 0;
        __syncthreads();
        sdata[threadIdx.x] += p;
        __syncthreads();
    }
    if (threadIdx.x < B) g_bsum[threadIdx.x] = sdata[threadIdx.x] - v;
}

__global__ void k_scan_add(int N, int E) {
    int i = blockIdx.x * blockDim.x + threadIdx.x;
    if (i < N) g_rowptr[i] += g_bsum[i / SCAN_ITEMS];
    if (i == 0) g_rowptr[N] = E;
}

__global__ void k_fill(const int* __restrict__ ei, int E) {
    int e = blockIdx.x * blockDim.x + threadIdx.x;
    if (e >= E) return;
    int s = ei[e];
    int d = ei[E + e];
    int pos = g_rowptr[d] + atomicAdd(&g_cursor[d], 1);
    g_esrc[pos] = s;
}

// ---------------- layer 1 input aggregation (3-wide) ----------------
__global__ void k_agg_x(int N) {
    int d = blockIdx.x * blockDim.x + threadIdx.x;
    if (d >= N) return;
    float a0 = g_xs[(size_t)d * 3 + 0];
    float a1 = g_xs[(size_t)d * 3 + 1];
    float a2 = g_xs[(size_t)d * 3 + 2];
    int beg = g_rowptr[d], end = g_rowptr[d + 1];
    for (int i = beg; i < end; i++) {
        int s = g_esrc[i];
        a0 += g_xs[(size_t)s * 3 + 0];
        a1 += g_xs[(size_t)s * 3 + 1];
        a2 += g_xs[(size_t)s * 3 + 2];
    }
    float di = g_dinv[d];
    g_xa[(size_t)d * 3 + 0] = di * a0;
    g_xa[(size_t)d * 3 + 1] = di * a1;
    g_xa[(size_t)d * 3 + 2] = di * a2;
}

// ---------------- GEMM phase: sh @ sW -> bf16 message buffer ----------------
__device__ __forceinline__ void gemm_phase_bf16(const float* sh, const float* sW,
                                                __nv_bfloat16* outBuf, int nodeBase, int N) {
    int tid = threadIdx.x;
    int m = tid >> 3;
    int g = tid & 7;
    unsigned long long a0 = 0ull, a1 = 0ull, a2 = 0ull, a3 = 0ull;
    unsigned long long b0 = 0ull, b1 = 0ull, b2 = 0ull, b3 = 0ull;
    const float* r0 = &sh[m * 68];
    const float* r1 = &sh[(m + 32) * 68];
    const float* wch = &sW[g * 10];
    #pragma unroll
    for (int k = 0; k < 64; k++) {
        float h0v = r0[k];
        float h1v = r1[k];
        unsigned long long h0 = pack2(h0v, h0v);
        unsigned long long h1 = pack2(h1v, h1v);
        const unsigned long long* w = (const unsigned long long*)(wch + k * 80);
        fma2(a0, h0, w[0]); fma2(a1, h0, w[1]); fma2(a2, h0, w[2]); fma2(a3, h0, w[3]);
        fma2(b0, h1, w[0]); fma2(b1, h1, w[1]); fma2(b2, h1, w[2]); fma2(b3, h1, w[3]);
    }

    int n0 = nodeBase + m;
    int n1 = nodeBase + m + 32;
    if (n0 < N) {
        float di = g_dinv[n0];
        float2 r00 = unpack2(a0), r01 = unpack2(a1), r02 = unpack2(a2), r03 = unpack2(a3);
        uint4 pkt;
        pkt.x = pack_bf16x2(r00.x * di, r00.y * di);
        pkt.y = pack_bf16x2(r01.x * di, r01.y * di);
        pkt.z = pack_bf16x2(r02.x * di, r02.y * di);
        pkt.w = pack_bf16x2(r03.x * di, r03.y * di);
        *(uint4*)(outBuf + (size_t)n0 * HDIM + g * 8) = pkt;
    }
    if (n1 < N) {
        float di = g_dinv[n1];
        float2 r10 = unpack2(b0), r11 = unpack2(b1), r12 = unpack2(b2), r13 = unpack2(b3);
        uint4 pkt;
        pkt.x = pack_bf16x2(r10.x * di, r10.y * di);
        pkt.y = pack_bf16x2(r11.x * di, r11.y * di);
        pkt.z = pack_bf16x2(r12.x * di, r12.y * di);
        pkt.w = pack_bf16x2(r13.x * di, r13.y * di);
        *(uint4*)(outBuf + (size_t)n1 * HDIM + g * 8) = pkt;
    }
}

// ---------------- kA: fused layer-1 + layer-2 transforms -> m0 ----------------
__global__ __launch_bounds__(256) void kA_l12(const float* __restrict__ W1,
                                              const float* __restrict__ b1,
                                              const float* __restrict__ W2, int N) {
    __shared__ __align__(16) float sW[64 * 80];
    __shared__ __align__(16) float sh[64 * 68];
    __shared__ float sW1[192];
    __shared__ float sb1[64];
    __shared__ float sxa[192];
    int tid = threadIdx.x;
    int nodeBase = blockIdx.x * 64;

    if (tid < 192) {
        sW1[tid] = W1[tid];
        int n = nodeBase + tid / 3;
        sxa[tid] = (n < N) ? g_xa[(size_t)nodeBase * 3 + tid] : 0.0f;
    }
    if (tid < 64) sb1[tid] = b1[tid];
    #pragma unroll
    for (int i = tid; i < 4096; i += 256) {
        int k = i >> 6, c = i & 63;
        sW[k * 80 + (c >> 3) * 10 + (c & 7)] = W2[i];
    }
    __syncthreads();

    #pragma unroll
    for (int i = tid; i < 4096; i += 256) {
        int n = i >> 6, c = i & 63;
        float v = sb1[c] + sxa[n * 3] * sW1[c] + sxa[n * 3 + 1] * sW1[64 + c]
                         + sxa[n * 3 + 2] * sW1[128 + c];
        sh[n * 68 + c] = fmaxf(v, 0.0f);
    }
    __syncthreads();

    gemm_phase_bf16(sh, sW, g_m0, nodeBase, N);
}

// ---------------- kB: fused layer-2 aggregation + layer-3 transform -> m1 ----------------
__global__ __launch_bounds__(256) void kB_agg_tr(const float* __restrict__ b2,
                                                 const float* __restrict__ W3, int N) {
    __shared__ __align__(16) float sW[64 * 80];
    __shared__ __align__(16) float sh[64 * 68];
    __shared__ float sb2[64];
    int tid = threadIdx.x;
    int nodeBase = blockIdx.x * 64;

    if (tid < 64) sb2[tid] = b2[tid];
    #pragma unroll
    for (int i = tid; i < 4096; i += 256) {
        int k = i >> 6, c = i & 63;
        sW[k * 80 + (c >> 3) * 10 + (c & 7)] = W3[i];
    }

    // aggregation: half-warp per node row; lane reads uint2 = 4 bf16 channels
    {
        int w    = tid >> 5;
        int lane = tid & 31;
        int half = lane >> 4;
        int l16  = lane & 15;
        #pragma unroll
        for (int j = 0; j < 4; j++) {
            int nl = w * 8 + j * 2 + half;
            int d  = nodeBase + nl;
            float a0 = 0.f, a1 = 0.f, a2 = 0.f, a3 = 0.f;
            float di = 0.0f;
            if (d < N) {
                uint2 v = ((const uint2*)(g_m0 + (size_t)d * HDIM))[l16];
                acc_bf16x2(a0, a1, v.x);
                acc_bf16x2(a2, a3, v.y);
                int beg = g_rowptr[d], end = g_rowptr[d + 1];
                for (int i = beg; i < end; i++) {
                    int s = g_esrc[i];
                    uint2 u = ((const uint2*)(g_m0 + (size_t)s * HDIM))[l16];
                    acc_bf16x2(a0, a1, u.x);
                    acc_bf16x2(a2, a3, u.y);
                }
                di = g_dinv[d];
            }
            float4 bb = ((const float4*)sb2)[l16];
            float4 r;
            r.x = fmaxf(bb.x + di * a0, 0.f);
            r.y = fmaxf(bb.y + di * a1, 0.f);
            r.z = fmaxf(bb.z + di * a2, 0.f);
            r.w = fmaxf(bb.w + di * a3, 0.f);
            *(float4*)&sh[nl * 68 + l16 * 4] = r;
        }
    }
    __syncthreads();

    gemm_phase_bf16(sh, sW, g_m1, nodeBase, N);
}

// ---------------- kC: fused layer-3 aggregation + relu + pool partials ----------------
__global__ __launch_bounds__(256) void kC_agg_pool(const float* __restrict__ b, int N) {
    int tid  = threadIdx.x;
    int warpInBlk = tid >> 5;
    int lane = tid & 31;
    int half = lane >> 4;
    int l16  = lane & 15;
    float4 bb = ((const float4*)b)[l16];
    float4 acc = make_float4(0.f, 0.f, 0.f, 0.f);

    int stride = gridDim.x * 16;
    for (int d = blockIdx.x * 16 + warpInBlk * 2 + half; d < N; d += stride) {
        float a0 = 0.f, a1 = 0.f, a2 = 0.f, a3 = 0.f;
        uint2 v = ((const uint2*)(g_m1 + (size_t)d * HDIM))[l16];
        acc_bf16x2(a0, a1, v.x);
        acc_bf16x2(a2, a3, v.y);
        int beg = g_rowptr[d], end = g_rowptr[d + 1];
        for (int i = beg; i < end; i++) {
            int s = g_esrc[i];
            uint2 u = ((const uint2*)(g_m1 + (size_t)s * HDIM))[l16];
            acc_bf16x2(a0, a1, u.x);
            acc_bf16x2(a2, a3, u.y);
        }
        float di = g_dinv[d];
        acc.x += fmaxf(bb.x + di * a0, 0.f);
        acc.y += fmaxf(bb.y + di * a1, 0.f);
        acc.z += fmaxf(bb.z + di * a2, 0.f);
        acc.w += fmaxf(bb.w + di * a3, 0.f);
    }

    __shared__ float sp[64];
    if (tid < 64) sp[tid] = 0.0f;
    __syncthreads();
    atomicAdd(&sp[l16 * 4 + 0], acc.x);
    atomicAdd(&sp[l16 * 4 + 1], acc.y);
    atomicAdd(&sp[l16 * 4 + 2], acc.z);
    atomicAdd(&sp[l16 * 4 + 3], acc.w);
    __syncthreads();
    if (tid < 64) g_partial[(size_t)blockIdx.x * HDIM + tid] = sp[tid];
}

__global__ __launch_bounds__(256) void k_reduce(int numPartial) {
    __shared__ float sdata[256];
    int c = blockIdx.x;
    float s = 0.0f;
    for (int i = threadIdx.x; i < numPartial; i += 256)
        s += g_partial[(size_t)i * HDIM + c];
    sdata[threadIdx.x] = s;
    __syncthreads();
    for (int off = 128; off > 0; off >>= 1) {
        if (threadIdx.x < off) sdata[threadIdx.x] += sdata[threadIdx.x + off];
        __syncthreads();
    }
    if (threadIdx.x == 0) g_pool[c] = sdata[0];
}

__global__ void k_final(const float* __restrict__ Wfc, const float* __restrict__ bfc,
                        float* __restrict__ out, int N) {
    int c = threadIdx.x;
    if (c >= 24) return;
    float invN = 1.0f / (float)N;
    float acc = bfc[c];
    #pragma unroll
    for (int k = 0; k < 64; k++)
        acc += (g_pool[k] * invN) * Wfc[k * 24 + c];
    out[c] = tanhf(acc);
}

// ---------------- launch ----------------
extern "C" void kernel_launch(void* const* d_in, const int* in_sizes, int n_in,
                              void* d_out, int out_size) {
    const float* x   = (const float*)d_in[0];
    const int*   ei  = (const int*)d_in[1];   // int32 (JAX x64 disabled)
    const float* W1  = (const float*)d_in[3];
    const float* b1  = (const float*)d_in[4];
    const float* W2  = (const float*)d_in[5];
    const float* b2  = (const float*)d_in[6];
    const float* W3  = (const float*)d_in[7];
    const float* b3  = (const float*)d_in[8];
    const float* Wfc = (const float*)d_in[9];
    const float* bfc = (const float*)d_in[10];
    float* out = (float*)d_out;

    int N = in_sizes[0] / 3;
    int E = in_sizes[1] / 2;

    const int T = 256;
    int nbN    = (N + T - 1) / T;
    int nbE    = (E + T - 1) / T;
    int nbTr   = (N + 63) / 64;
    int nbScan = (N + SCAN_ITEMS - 1) / SCAN_ITEMS;

    // CSR + normalization
    k_zero<<<nbN, T>>>(N);
    k_hist<<<nbE, T>>>(ei, E);
    k_prep<<<nbN, T>>>(x, N);
    k_scan_local<<<nbScan, SCAN_T>>>(N);
    k_scan_bsums<<<1, SCAN_T>>>(nbScan);
    k_scan_add<<<nbN, T>>>(N, E);
    k_fill<<<nbE, T>>>(ei, E);

    // layer 1 aggregation (3-wide)
    k_agg_x<<<nbN, T>>>(N);

    // fused layer1+layer2 transforms -> m0 (bf16)
    kA_l12<<<nbTr, T>>>(W1, b1, W2, N);

    // fused layer2 aggregation + layer3 transform -> m1 (bf16)
    kB_agg_tr<<<nbTr, T>>>(b2, W3, N);

    // fused layer3 aggregation + relu + mean-pool
    kC_agg_pool<<<POOL_BLOCKS, T>>>(b3, N);

    // reduce + FC + tanh
    k_reduce<<<64, 256>>>(POOL_BLOCKS);
    k_final<<<1, 32>>>(Wfc, bfc, out, N);
}

// round 7
// speedup vs baseline: 4.4077x; 1.0201x over previous
#include <cuda_runtime.h>
#include <cuda_bf16.h>
#include <math.h>

#define MAX_N 500000
#define MAX_E 1000000
#define HDIM  64
#define SCAN_T 512
#define SCAN_ITEMS 1024
#define POOL_BLOCKS 2960

// ---------------- device scratch ----------------
__device__ __nv_bfloat16 g_m0[(size_t)MAX_N * HDIM];  // layer-2 messages (bf16)
__device__ __nv_bfloat16 g_m1[(size_t)MAX_N * HDIM];  // layer-3 messages (bf16)
__device__ float g_dinv[MAX_N];
__device__ float4 g_xs4[MAX_N];                       // dinv-scaled input (padded)
__device__ float4 g_xa4[MAX_N];                       // aggregated input (padded)
__device__ int   g_degi[MAX_N];
__device__ int   g_rowptr[MAX_N + 1];
__device__ int   g_cursor[MAX_N];
__device__ int   g_esrc[MAX_E];
__device__ int   g_bsum[1024];
__device__ float g_partial[(size_t)POOL_BLOCKS * HDIM];
__device__ float g_pool[HDIM];

// ---------------- packed helpers ----------------
__device__ __forceinline__ unsigned long long pack2(float a, float b) {
    unsigned long long r;
    asm("mov.b64 %0, {%1, %2};" : "=l"(r) : "f"(a), "f"(b));
    return r;
}
__device__ __forceinline__ void fma2(unsigned long long& d, unsigned long long a, unsigned long long b) {
    asm("fma.rn.f32x2 %0, %1, %2, %0;" : "+l"(d) : "l"(a), "l"(b));
}
__device__ __forceinline__ float2 unpack2(unsigned long long v) {
    float2 f;
    asm("mov.b64 {%0, %1}, %2;" : "=f"(f.x), "=f"(f.y) : "l"(v));
    return f;
}
__device__ __forceinline__ unsigned pack_bf16x2(float lo, float hi) {
    unsigned r;
    asm("cvt.rn.bf16x2.f32 %0, %1, %2;" : "=r"(r) : "f"(hi), "f"(lo));
    return r;
}
__device__ __forceinline__ void acc_bf16x2(float& a0, float& a1, unsigned v) {
    __nv_bfloat162 b = *reinterpret_cast<__nv_bfloat162*>(&v);
    float2 f = __bfloat1622float2(b);
    a0 += f.x; a1 += f.y;
}
__device__ __forceinline__ void acc_uint4(float* a, uint4 v) {
    acc_bf16x2(a[0], a[1], v.x);
    acc_bf16x2(a[2], a[3], v.y);
    acc_bf16x2(a[4], a[5], v.z);
    acc_bf16x2(a[6], a[7], v.w);
}

// ---------------- degree / prep / CSR ----------------
__global__ void k_zero(int N) {
    int i = blockIdx.x * blockDim.x + threadIdx.x;
    if (i < N) { g_degi[i] = 0; g_cursor[i] = 0; }
}

__global__ void k_hist(const int* __restrict__ ei, int E) {
    int e = blockIdx.x * blockDim.x + threadIdx.x;
    if (e < E) atomicAdd(&g_degi[ei[E + e]], 1);
}

__global__ void k_prep(const float* __restrict__ x, int N) {
    int i = blockIdx.x * blockDim.x + threadIdx.x;
    if (i >= N) return;
    float di = rsqrtf((float)(g_degi[i] + 1));
    g_dinv[i] = di;
    g_xs4[i] = make_float4(di * x[(size_t)i * 3 + 0],
                           di * x[(size_t)i * 3 + 1],
                           di * x[(size_t)i * 3 + 2], 0.0f);
}

__global__ __launch_bounds__(SCAN_T) void k_scan_local(int N) {
    __shared__ int sdata[SCAN_T];
    int base = blockIdx.x * SCAN_ITEMS;
    int i0 = base + threadIdx.x * 2;
    int d0 = (i0     < N) ? g_degi[i0]     : 0;
    int d1 = (i0 + 1 < N) ? g_degi[i0 + 1] : 0;
    int tsum = d0 + d1;
    sdata[threadIdx.x] = tsum;
    __syncthreads();
    for (int off = 1; off < SCAN_T; off <<= 1) {
        int v = (threadIdx.x >= off) ? sdata[threadIdx.x - off] : 0;
        __syncthreads();
        sdata[threadIdx.x] += v;
        __syncthreads();
    }
    int excl = sdata[threadIdx.x] - tsum;
    if (i0     < N) g_rowptr[i0]     = excl;
    if (i0 + 1 < N) g_rowptr[i0 + 1] = excl + d0;
    if (threadIdx.x == SCAN_T - 1) g_bsum[blockIdx.x] = sdata[SCAN_T - 1];
}

__global__ __launch_bounds__(SCAN_T) void k_scan_bsums(int B) {
    __shared__ int sdata[SCAN_T];
    int v = (threadIdx.x < B) ? g_bsum[threadIdx.x] : 0;
    sdata[threadIdx.x] = v;
    __syncthreads();
    for (int off = 1; off < SCAN_T; off <<= 1) {
        int p = (threadIdx.x >= off) ? sdata[threadIdx.x - off] : 0;
        __syncthreads();
        sdata[threadIdx.x] += p;
        __syncthreads();
    }
    if (threadIdx.x < B) g_bsum[threadIdx.x] = sdata[threadIdx.x] - v;
}

__global__ void k_scan_add(int N, int E) {
    int i = blockIdx.x * blockDim.x + threadIdx.x;
    if (i < N) g_rowptr[i] += g_bsum[i / SCAN_ITEMS];
    if (i == 0) g_rowptr[N] = E;
}

__global__ void k_fill(const int* __restrict__ ei, int E) {
    int e = blockIdx.x * blockDim.x + threadIdx.x;
    if (e >= E) return;
    int s = ei[e];
    int d = ei[E + e];
    int pos = g_rowptr[d] + atomicAdd(&g_cursor[d], 1);
    g_esrc[pos] = s;
}

// ---------------- layer 1 input aggregation (float4 rows) ----------------
__global__ void k_agg_x(int N) {
    int d = blockIdx.x * blockDim.x + threadIdx.x;
    if (d >= N) return;
    float4 a = g_xs4[d];
    int beg = g_rowptr[d], end = g_rowptr[d + 1];
    for (int i = beg; i < end; i++) {
        float4 v = g_xs4[g_esrc[i]];
        a.x += v.x; a.y += v.y; a.z += v.z;
    }
    float di = g_dinv[d];
    g_xa4[d] = make_float4(di * a.x, di * a.y, di * a.z, 0.0f);
}

// ---------------- GEMM phase: sh @ sW -> bf16 message buffer ----------------
__device__ __forceinline__ void gemm_phase_bf16(const float* sh, const float* sW,
                                                __nv_bfloat16* outBuf, int nodeBase, int N) {
    int tid = threadIdx.x;
    int m = tid >> 3;
    int g = tid & 7;
    unsigned long long a0 = 0ull, a1 = 0ull, a2 = 0ull, a3 = 0ull;
    unsigned long long b0 = 0ull, b1 = 0ull, b2 = 0ull, b3 = 0ull;
    const float* r0 = &sh[m * 68];
    const float* r1 = &sh[(m + 32) * 68];
    const float* wch = &sW[g * 10];
    #pragma unroll
    for (int k = 0; k < 64; k++) {
        float h0v = r0[k];
        float h1v = r1[k];
        unsigned long long h0 = pack2(h0v, h0v);
        unsigned long long h1 = pack2(h1v, h1v);
        const unsigned long long* w = (const unsigned long long*)(wch + k * 80);
        fma2(a0, h0, w[0]); fma2(a1, h0, w[1]); fma2(a2, h0, w[2]); fma2(a3, h0, w[3]);
        fma2(b0, h1, w[0]); fma2(b1, h1, w[1]); fma2(b2, h1, w[2]); fma2(b3, h1, w[3]);
    }

    int n0 = nodeBase + m;
    int n1 = nodeBase + m + 32;
    if (n0 < N) {
        float di = g_dinv[n0];
        float2 r00 = unpack2(a0), r01 = unpack2(a1), r02 = unpack2(a2), r03 = unpack2(a3);
        uint4 pkt;
        pkt.x = pack_bf16x2(r00.x * di, r00.y * di);
        pkt.y = pack_bf16x2(r01.x * di, r01.y * di);
        pkt.z = pack_bf16x2(r02.x * di, r02.y * di);
        pkt.w = pack_bf16x2(r03.x * di, r03.y * di);
        *(uint4*)(outBuf + (size_t)n0 * HDIM + g * 8) = pkt;
    }
    if (n1 < N) {
        float di = g_dinv[n1];
        float2 r10 = unpack2(b0), r11 = unpack2(b1), r12 = unpack2(b2), r13 = unpack2(b3);
        uint4 pkt;
        pkt.x = pack_bf16x2(r10.x * di, r10.y * di);
        pkt.y = pack_bf16x2(r11.x * di, r11.y * di);
        pkt.z = pack_bf16x2(r12.x * di, r12.y * di);
        pkt.w = pack_bf16x2(r13.x * di, r13.y * di);
        *(uint4*)(outBuf + (size_t)n1 * HDIM + g * 8) = pkt;
    }
}

// ---------------- kA: fused layer-1 + layer-2 transforms -> m0 ----------------
__global__ __launch_bounds__(256) void kA_l12(const float* __restrict__ W1,
                                              const float* __restrict__ b1,
                                              const float* __restrict__ W2, int N) {
    __shared__ __align__(16) float sW[64 * 80];
    __shared__ __align__(16) float sh[64 * 68];
    __shared__ float4 sxa[64];
    __shared__ float sW1[192];
    __shared__ float sb1[64];
    int tid = threadIdx.x;
    int nodeBase = blockIdx.x * 64;

    if (tid < 192) sW1[tid] = W1[tid];
    if (tid < 64) {
        sb1[tid] = b1[tid];
        int n = nodeBase + tid;
        sxa[tid] = (n < N) ? g_xa4[n] : make_float4(0.f, 0.f, 0.f, 0.f);
    }
    #pragma unroll
    for (int i = tid; i < 4096; i += 256) {
        int k = i >> 6, c = i & 63;
        sW[k * 80 + (c >> 3) * 10 + (c & 7)] = W2[i];
    }
    __syncthreads();

    #pragma unroll
    for (int i = tid; i < 4096; i += 256) {
        int n = i >> 6, c = i & 63;
        float4 xa = sxa[n];
        float v = sb1[c] + xa.x * sW1[c] + xa.y * sW1[64 + c] + xa.z * sW1[128 + c];
        sh[n * 68 + c] = fmaxf(v, 0.0f);
    }
    __syncthreads();

    gemm_phase_bf16(sh, sW, g_m0, nodeBase, N);
}

// ---------------- kB: fused layer-2 aggregation + layer-3 transform -> m1 ----------------
// aggregation: octet (8 lanes) per node row, lane reads uint4 = 8 bf16 channels
__global__ __launch_bounds__(256) void kB_agg_tr(const float* __restrict__ b2,
                                                 const float* __restrict__ W3, int N) {
    __shared__ __align__(16) float sW[64 * 80];
    __shared__ __align__(16) float sh[64 * 68];
    __shared__ float sb2[64];
    int tid = threadIdx.x;
    int nodeBase = blockIdx.x * 64;

    if (tid < 64) sb2[tid] = b2[tid];
    #pragma unroll
    for (int i = tid; i < 4096; i += 256) {
        int k = i >> 6, c = i & 63;
        sW[k * 80 + (c >> 3) * 10 + (c & 7)] = W3[i];
    }

    {
        int w    = tid >> 5;       // warp 0..7
        int lane = tid & 31;
        int oct  = lane >> 3;      // 0..3
        int l8   = lane & 7;
        #pragma unroll
        for (int j = 0; j < 2; j++) {
            int nl = w * 8 + j * 4 + oct;     // local node 0..63
            int d  = nodeBase + nl;
            float a[8] = {0.f, 0.f, 0.f, 0.f, 0.f, 0.f, 0.f, 0.f};
            float di = 0.0f;
            if (d < N) {
                acc_uint4(a, ((const uint4*)(g_m0 + (size_t)d * HDIM))[l8]);
                int beg = g_rowptr[d], end = g_rowptr[d + 1];
                for (int i = beg; i < end; i++) {
                    int s = g_esrc[i];
                    acc_uint4(a, ((const uint4*)(g_m0 + (size_t)s * HDIM))[l8]);
                }
                di = g_dinv[d];
            }
            const float* bb = &sb2[l8 * 8];
            float4 r0, r1;
            r0.x = fmaxf(bb[0] + di * a[0], 0.f);
            r0.y = fmaxf(bb[1] + di * a[1], 0.f);
            r0.z = fmaxf(bb[2] + di * a[2], 0.f);
            r0.w = fmaxf(bb[3] + di * a[3], 0.f);
            r1.x = fmaxf(bb[4] + di * a[4], 0.f);
            r1.y = fmaxf(bb[5] + di * a[5], 0.f);
            r1.z = fmaxf(bb[6] + di * a[6], 0.f);
            r1.w = fmaxf(bb[7] + di * a[7], 0.f);
            *(float4*)&sh[nl * 68 + l8 * 8]     = r0;
            *(float4*)&sh[nl * 68 + l8 * 8 + 4] = r1;
        }
    }
    __syncthreads();

    gemm_phase_bf16(sh, sW, g_m1, nodeBase, N);
}

// ---------------- kC: fused layer-3 aggregation + relu + pool partials ----------------
__global__ __launch_bounds__(256) void kC_agg_pool(const float* __restrict__ b, int N) {
    int tid  = threadIdx.x;
    int w    = tid >> 5;
    int lane = tid & 31;
    int oct  = lane >> 3;
    int l8   = lane & 7;

    float bb[8];
    #pragma unroll
    for (int k = 0; k < 8; k++) bb[k] = b[l8 * 8 + k];
    float acc[8] = {0.f, 0.f, 0.f, 0.f, 0.f, 0.f, 0.f, 0.f};

    int stride = gridDim.x * 32;
    for (int d = blockIdx.x * 32 + w * 4 + oct; d < N; d += stride) {
        float a[8] = {0.f, 0.f, 0.f, 0.f, 0.f, 0.f, 0.f, 0.f};
        acc_uint4(a, ((const uint4*)(g_m1 + (size_t)d * HDIM))[l8]);
        int beg = g_rowptr[d], end = g_rowptr[d + 1];
        for (int i = beg; i < end; i++) {
            int s = g_esrc[i];
            acc_uint4(a, ((const uint4*)(g_m1 + (size_t)s * HDIM))[l8]);
        }
        float di = g_dinv[d];
        #pragma unroll
        for (int k = 0; k < 8; k++)
            acc[k] += fmaxf(bb[k] + di * a[k], 0.f);
    }

    __shared__ float sp[64];
    if (tid < 64) sp[tid] = 0.0f;
    __syncthreads();
    #pragma unroll
    for (int k = 0; k < 8; k++)
        atomicAdd(&sp[l8 * 8 + k], acc[k]);
    __syncthreads();
    if (tid < 64) g_partial[(size_t)blockIdx.x * HDIM + tid] = sp[tid];
}

__global__ __launch_bounds__(256) void k_reduce(int numPartial) {
    __shared__ float sdata[256];
    int c = blockIdx.x;
    float s = 0.0f;
    for (int i = threadIdx.x; i < numPartial; i += 256)
        s += g_partial[(size_t)i * HDIM + c];
    sdata[threadIdx.x] = s;
    __syncthreads();
    for (int off = 128; off > 0; off >>= 1) {
        if (threadIdx.x < off) sdata[threadIdx.x] += sdata[threadIdx.x + off];
        __syncthreads();
    }
    if (threadIdx.x == 0) g_pool[c] = sdata[0];
}

__global__ void k_final(const float* __restrict__ Wfc, const float* __restrict__ bfc,
                        float* __restrict__ out, int N) {
    int c = threadIdx.x;
    if (c >= 24) return;
    float invN = 1.0f / (float)N;
    float acc = bfc[c];
    #pragma unroll
    for (int k = 0; k < 64; k++)
        acc += (g_pool[k] * invN) * Wfc[k * 24 + c];
    out[c] = tanhf(acc);
}

// ---------------- launch ----------------
extern "C" void kernel_launch(void* const* d_in, const int* in_sizes, int n_in,
                              void* d_out, int out_size) {
    const float* x   = (const float*)d_in[0];
    const int*   ei  = (const int*)d_in[1];   // int32 (JAX x64 disabled)
    const float* W1  = (const float*)d_in[3];
    const float* b1  = (const float*)d_in[4];
    const float* W2  = (const float*)d_in[5];
    const float* b2  = (const float*)d_in[6];
    const float* W3  = (const float*)d_in[7];
    const float* b3  = (const float*)d_in[8];
    const float* Wfc = (const float*)d_in[9];
    const float* bfc = (const float*)d_in[10];
    float* out = (float*)d_out;

    int N = in_sizes[0] / 3;
    int E = in_sizes[1] / 2;

    const int T = 256;
    int nbN    = (N + T - 1) / T;
    int nbE    = (E + T - 1) / T;
    int nbTr   = (N + 63) / 64;
    int nbScan = (N + SCAN_ITEMS - 1) / SCAN_ITEMS;

    // CSR + normalization
    k_zero<<<nbN, T>>>(N);
    k_hist<<<nbE, T>>>(ei, E);
    k_prep<<<nbN, T>>>(x, N);
    k_scan_local<<<nbScan, SCAN_T>>>(N);
    k_scan_bsums<<<1, SCAN_T>>>(nbScan);
    k_scan_add<<<nbN, T>>>(N, E);
    k_fill<<<nbE, T>>>(ei, E);

    // layer 1 aggregation (float4 rows)
    k_agg_x<<<nbN, T>>>(N);

    // fused layer1+layer2 transforms -> m0 (bf16)
    kA_l12<<<nbTr, T>>>(W1, b1, W2, N);

    // fused layer2 aggregation + layer3 transform -> m1 (bf16)
    kB_agg_tr<<<nbTr, T>>>(b2, W3, N);

    // fused layer3 aggregation + relu + mean-pool
    kC_agg_pool<<<POOL_BLOCKS, T>>>(b3, N);

    // reduce + FC + tanh
    k_reduce<<<64, 256>>>(POOL_BLOCKS);
    k_final<<<1, 32>>>(Wfc, bfc, out, N);
}

// round 10
// speedup vs baseline: 6.2516x; 1.4183x over previous
#include <cuda_runtime.h>
#include <cuda_bf16.h>
#include <cstdint>
#include <math.h>

#define MAX_N 500000
#define MAX_E 1000000
#define HDIM  64
#define SCAN_T 512
#define SCAN_ITEMS 1024
#define POOL_BLOCKS 2960

// ---------------- device scratch ----------------
__device__ __nv_bfloat16 g_m0[(size_t)MAX_N * HDIM];  // layer-2 messages (bf16)
__device__ __nv_bfloat16 g_m1[(size_t)MAX_N * HDIM];  // layer-3 messages (bf16)
__device__ float g_dinv[MAX_N];
__device__ float4 g_xs4[MAX_N];
__device__ float4 g_xa4[MAX_N];
__device__ int   g_degi[MAX_N];
__device__ int   g_rowptr[MAX_N + 1];
__device__ int   g_cursor[MAX_N];
__device__ int   g_esrc[MAX_E];
__device__ int   g_bsum[1024];
__device__ float g_partial[(size_t)POOL_BLOCKS * HDIM];
__device__ float g_pool[HDIM];

// ---------------- helpers ----------------
__device__ __forceinline__ unsigned pack_bf16x2(float lo, float hi) {
    unsigned r;
    asm("cvt.rn.bf16x2.f32 %0, %1, %2;" : "=r"(r) : "f"(hi), "f"(lo));
    return r;
}
__device__ __forceinline__ void acc_bf16x2(float& a0, float& a1, unsigned v) {
    __nv_bfloat162 b = *reinterpret_cast<__nv_bfloat162*>(&v);
    float2 f = __bfloat1622float2(b);
    a0 += f.x; a1 += f.y;
}
__device__ __forceinline__ void acc_uint4(float* a, uint4 v) {
    acc_bf16x2(a[0], a[1], v.x);
    acc_bf16x2(a[2], a[3], v.y);
    acc_bf16x2(a[4], a[5], v.z);
    acc_bf16x2(a[6], a[7], v.w);
}
__device__ __forceinline__ uint32_t f2tf32(float f) {
    uint32_t r;
    asm("cvt.rna.tf32.f32 %0, %1;" : "=r"(r) : "f"(f));
    return r;
}
__device__ __forceinline__ void mma_tf32(float* d, uint32_t a0, uint32_t a1, uint32_t a2,
                                         uint32_t a3, uint32_t b0, uint32_t b1) {
    asm volatile("mma.sync.aligned.m16n8k8.row.col.f32.tf32.tf32.f32 "
                 "{%0,%1,%2,%3}, {%4,%5,%6,%7}, {%8,%9}, {%0,%1,%2,%3};"
                 : "+f"(d[0]), "+f"(d[1]), "+f"(d[2]), "+f"(d[3])
                 : "r"(a0), "r"(a1), "r"(a2), "r"(a3), "r"(b0), "r"(b1));
}

#define AROW 68   // fp32/tf32 smem row stride (floats)

// ---------------- degree / prep / CSR ----------------
__global__ void k_zero(int N) {
    int i = blockIdx.x * blockDim.x + threadIdx.x;
    if (i < N) { g_degi[i] = 0; g_cursor[i] = 0; }
}

__global__ void k_hist(const int* __restrict__ ei, int E) {
    int e = blockIdx.x * blockDim.x + threadIdx.x;
    if (e < E) atomicAdd(&g_degi[ei[E + e]], 1);
}

__global__ void k_prep(const float* __restrict__ x, int N) {
    int i = blockIdx.x * blockDim.x + threadIdx.x;
    if (i >= N) return;
    float di = rsqrtf((float)(g_degi[i] + 1));
    g_dinv[i] = di;
    g_xs4[i] = make_float4(di * x[(size_t)i * 3 + 0],
                           di * x[(size_t)i * 3 + 1],
                           di * x[(size_t)i * 3 + 2], 0.0f);
}

__global__ __launch_bounds__(SCAN_T) void k_scan_local(int N) {
    __shared__ int sdata[SCAN_T];
    int base = blockIdx.x * SCAN_ITEMS;
    int i0 = base + threadIdx.x * 2;
    int d0 = (i0     < N) ? g_degi[i0]     : 0;
    int d1 = (i0 + 1 < N) ? g_degi[i0 + 1] : 0;
    int tsum = d0 + d1;
    sdata[threadIdx.x] = tsum;
    __syncthreads();
    for (int off = 1; off < SCAN_T; off <<= 1) {
        int v = (threadIdx.x >= off) ? sdata[threadIdx.x - off] : 0;
        __syncthreads();
        sdata[threadIdx.x] += v;
        __syncthreads();
    }
    int excl = sdata[threadIdx.x] - tsum;
    if (i0     < N) g_rowptr[i0]     = excl;
    if (i0 + 1 < N) g_rowptr[i0 + 1] = excl + d0;
    if (threadIdx.x == SCAN_T - 1) g_bsum[blockIdx.x] = sdata[SCAN_T - 1];
}

__global__ __launch_bounds__(SCAN_T) void k_scan_bsums(int B) {
    __shared__ int sdata[SCAN_T];
    int v = (threadIdx.x < B) ? g_bsum[threadIdx.x] : 0;
    sdata[threadIdx.x] = v;
    __syncthreads();
    for (int off = 1; off < SCAN_T; off <<= 1) {
        int p = (threadIdx.x >= off) ? sdata[threadIdx.x - off] : 0;
        __syncthreads();
        sdata[threadIdx.x] += p;
        __syncthreads();
    }
    if (threadIdx.x < B) g_bsum[threadIdx.x] = sdata[threadIdx.x] - v;
}

__global__ void k_scan_add(int N, int E) {
    int i = blockIdx.x * blockDim.x + threadIdx.x;
    if (i < N) g_rowptr[i] += g_bsum[i / SCAN_ITEMS];
    if (i == 0) g_rowptr[N] = E;
}

__global__ void k_fill(const int* __restrict__ ei, int E) {
    int e = blockIdx.x * blockDim.x + threadIdx.x;
    if (e >= E) return;
    int s = ei[e];
    int d = ei[E + e];
    int pos = g_rowptr[d] + atomicAdd(&g_cursor[d], 1);
    g_esrc[pos] = s;
}

// ---------------- layer 1 input aggregation (float4 rows) ----------------
__global__ void k_agg_x(int N) {
    int d = blockIdx.x * blockDim.x + threadIdx.x;
    if (d >= N) return;
    float4 a = g_xs4[d];
    int beg = g_rowptr[d], end = g_rowptr[d + 1];
    for (int i = beg; i < end; i++) {
        float4 v = g_xs4[g_esrc[i]];
        a.x += v.x; a.y += v.y; a.z += v.z;
    }
    float di = g_dinv[d];
    g_xa4[d] = make_float4(di * a.x, di * a.y, di * a.z, 0.0f);
}

// ---------------- tf32 tensor-core GEMM phase ----------------
// sA: 64x64 tf32 (row=node, col=k), stride AROW u32. sB: 64x64 tf32 (row=k, col=ch).
// D = dinv * (A @ B), packed bf16 -> outBuf. sC: u32[64][36] staging.
__device__ __forceinline__ void gemm_mma(const uint32_t* sA, const uint32_t* sB,
                                         uint32_t* sC, const float* sdinv,
                                         __nv_bfloat16* outBuf, int nodeBase, int N) {
    int tid  = threadIdx.x;
    int w    = tid >> 5;
    int lane = tid & 31;
    int mw = w & 3;          // M16 tile index
    int nw = w >> 2;         // N32 tile index
    int g  = lane >> 2;      // group 0..7
    int t  = lane & 3;       // thread-in-group

    float d[4][4];
    #pragma unroll
    for (int i = 0; i < 4; i++)
        #pragma unroll
        for (int j = 0; j < 4; j++) d[i][j] = 0.0f;

    const uint32_t* aRow0 = sA + (mw * 16 + g) * AROW;      // row g
    const uint32_t* aRow1 = aRow0 + 8 * AROW;               // row g+8
    int nbase = nw * 32 + g;

    #pragma unroll
    for (int kt = 0; kt < 8; kt++) {
        int k0 = kt * 8 + t;
        uint32_t a0 = aRow0[k0];
        uint32_t a1 = aRow1[k0];
        uint32_t a2 = aRow0[k0 + 4];
        uint32_t a3 = aRow1[k0 + 4];
        const uint32_t* b0p = sB + k0 * AROW + nbase;
        const uint32_t* b1p = b0p + 4 * AROW;
        #pragma unroll
        for (int nt = 0; nt < 4; nt++) {
            mma_tf32(d[nt], a0, a1, a2, a3, b0p[nt * 8], b1p[nt * 8]);
        }
    }

    // epilogue: scale by dinv, pack bf16x2, stage in sC (row stride 36 u32)
    int r0 = mw * 16 + g;
    int r1 = r0 + 8;
    float di0 = sdinv[r0], di1 = sdinv[r1];
    #pragma unroll
    for (int nt = 0; nt < 4; nt++) {
        int cp = nw * 16 + nt * 4 + t;
        sC[r0 * 36 + cp] = pack_bf16x2(d[nt][0] * di0, d[nt][1] * di0);
        sC[r1 * 36 + cp] = pack_bf16x2(d[nt][2] * di1, d[nt][3] * di1);
    }
    __syncthreads();

    int r = tid >> 2, q = tid & 3;
    if (nodeBase + r < N) {
        uint4 v0 = *(uint4*)&sC[r * 36 + q * 8];
        uint4 v1 = *(uint4*)&sC[r * 36 + q * 8 + 4];
        __nv_bfloat16* o = outBuf + (size_t)(nodeBase + r) * HDIM + q * 16;
        *(uint4*)o       = v0;
        *((uint4*)o + 1) = v1;
    }
}

// load W (f32 64x64 row-major) -> sB tf32, stride AROW
__device__ __forceinline__ void load_W_tf32(const float* __restrict__ W, uint32_t* sB) {
    int tid = threadIdx.x;
    #pragma unroll
    for (int i = tid; i < 1024; i += 256) {
        int k = i >> 4, cq = i & 15;
        float4 wv = ((const float4*)W)[i];
        uint32_t* o = sB + k * AROW + cq * 4;
        o[0] = f2tf32(wv.x); o[1] = f2tf32(wv.y);
        o[2] = f2tf32(wv.z); o[3] = f2tf32(wv.w);
    }
}

__device__ __forceinline__ void load_dinv(float* sdinv, int nodeBase, int N) {
    int tid = threadIdx.x;
    if (tid < 64) {
        int n = nodeBase + tid;
        sdinv[tid] = (n < N) ? g_dinv[n] : 0.0f;
    }
}

// ---------------- kA: fused layer-1 + layer-2 transforms -> m0 ----------------
__global__ __launch_bounds__(256) void kA_l12(const float* __restrict__ W1,
                                              const float* __restrict__ b1,
                                              const float* __restrict__ W2, int N) {
    __shared__ __align__(16) uint32_t sA[64 * AROW];
    __shared__ __align__(16) uint32_t sB[64 * AROW];
    __shared__ __align__(16) uint32_t sC[64 * 36];
    __shared__ float4 sxa[64];
    __shared__ float sW1[192];
    __shared__ float sb1[64];
    __shared__ float sdinv[64];
    int tid = threadIdx.x;
    int nodeBase = blockIdx.x * 64;

    if (tid < 192) sW1[tid] = W1[tid];
    if (tid < 64) {
        sb1[tid] = b1[tid];
        int n = nodeBase + tid;
        sxa[tid] = (n < N) ? g_xa4[n] : make_float4(0.f, 0.f, 0.f, 0.f);
    }
    load_dinv(sdinv, nodeBase, N);
    load_W_tf32(W2, sB);
    __syncthreads();

    // phase 1: sA[n][c] = tf32(relu(xa @ W1 + b1))
    #pragma unroll
    for (int i = tid; i < 4096; i += 256) {
        int n = i >> 6, c = i & 63;
        float4 xa = sxa[n];
        float v = sb1[c] + xa.x * sW1[c] + xa.y * sW1[64 + c] + xa.z * sW1[128 + c];
        sA[n * AROW + c] = f2tf32(fmaxf(v, 0.0f));
    }
    __syncthreads();

    gemm_mma(sA, sB, sC, sdinv, g_m0, nodeBase, N);
}

// ---------------- kB: fused layer-2 aggregation + layer-3 transform -> m1 ----------------
__global__ __launch_bounds__(256) void kB_agg_tr(const float* __restrict__ b2,
                                                 const float* __restrict__ W3, int N) {
    __shared__ __align__(16) uint32_t sA[64 * AROW];
    __shared__ __align__(16) uint32_t sB[64 * AROW];
    __shared__ __align__(16) uint32_t sC[64 * 36];
    __shared__ float sb2[64];
    __shared__ float sdinv[64];
    int tid = threadIdx.x;
    int nodeBase = blockIdx.x * 64;

    if (tid < 64) sb2[tid] = b2[tid];
    load_dinv(sdinv, nodeBase, N);
    load_W_tf32(W3, sB);

    // aggregation: octet (8 lanes) per node row, lane reads uint4 = 8 bf16 channels
    {
        int w    = tid >> 5;
        int lane = tid & 31;
        int oct  = lane >> 3;
        int l8   = lane & 7;
        #pragma unroll
        for (int j = 0; j < 2; j++) {
            int nl = w * 8 + j * 4 + oct;
            int d  = nodeBase + nl;
            float a[8] = {0.f, 0.f, 0.f, 0.f, 0.f, 0.f, 0.f, 0.f};
            float di = 0.0f;
            if (d < N) {
                acc_uint4(a, ((const uint4*)(g_m0 + (size_t)d * HDIM))[l8]);
                int beg = g_rowptr[d], end = g_rowptr[d + 1];
                for (int i = beg; i < end; i++) {
                    int s = g_esrc[i];
                    acc_uint4(a, ((const uint4*)(g_m0 + (size_t)s * HDIM))[l8]);
                }
                di = g_dinv[d];
            }
            const float* bb = &sb2[l8 * 8];
            uint32_t* o = sA + nl * AROW + l8 * 8;
            #pragma unroll
            for (int k = 0; k < 8; k++)
                o[k] = f2tf32(fmaxf(bb[k] + di * a[k], 0.f));
        }
    }
    __syncthreads();

    gemm_mma(sA, sB, sC, sdinv, g_m1, nodeBase, N);
}

// ---------------- kC: fused layer-3 aggregation + relu + pool partials ----------------
__global__ __launch_bounds__(256) void kC_agg_pool(const float* __restrict__ b, int N) {
    int tid  = threadIdx.x;
    int w    = tid >> 5;
    int lane = tid & 31;
    int oct  = lane >> 3;
    int l8   = lane & 7;

    float bb[8];
    #pragma unroll
    for (int k = 0; k < 8; k++) bb[k] = b[l8 * 8 + k];
    float acc[8] = {0.f, 0.f, 0.f, 0.f, 0.f, 0.f, 0.f, 0.f};

    int stride = gridDim.x * 32;
    for (int d = blockIdx.x * 32 + w * 4 + oct; d < N; d += stride) {
        float a[8] = {0.f, 0.f, 0.f, 0.f, 0.f, 0.f, 0.f, 0.f};
        acc_uint4(a, ((const uint4*)(g_m1 + (size_t)d * HDIM))[l8]);
        int beg = g_rowptr[d], end = g_rowptr[d + 1];
        for (int i = beg; i < end; i++) {
            int s = g_esrc[i];
            acc_uint4(a, ((const uint4*)(g_m1 + (size_t)s * HDIM))[l8]);
        }
        float di = g_dinv[d];
        #pragma unroll
        for (int k = 0; k < 8; k++)
            acc[k] += fmaxf(bb[k] + di * a[k], 0.f);
    }

    __shared__ float sp[64];
    if (tid < 64) sp[tid] = 0.0f;
    __syncthreads();
    #pragma unroll
    for (int k = 0; k < 8; k++)
        atomicAdd(&sp[l8 * 8 + k], acc[k]);
    __syncthreads();
    if (tid < 64) g_partial[(size_t)blockIdx.x * HDIM + tid] = sp[tid];
}

__global__ __launch_bounds__(256) void k_reduce(int numPartial) {
    __shared__ float sdata[256];
    int c = blockIdx.x;
    float s = 0.0f;
    for (int i = threadIdx.x; i < numPartial; i += 256)
        s += g_partial[(size_t)i * HDIM + c];
    sdata[threadIdx.x] = s;
    __syncthreads();
    for (int off = 128; off > 0; off >>= 1) {
        if (threadIdx.x < off) sdata[threadIdx.x] += sdata[threadIdx.x + off];
        __syncthreads();
    }
    if (threadIdx.x == 0) g_pool[c] = sdata[0];
}

__global__ void k_final(const float* __restrict__ Wfc, const float* __restrict__ bfc,
                        float* __restrict__ out, int N) {
    int c = threadIdx.x;
    if (c >= 24) return;
    float invN = 1.0f / (float)N;
    float acc = bfc[c];
    #pragma unroll
    for (int k = 0; k < 64; k++)
        acc += (g_pool[k] * invN) * Wfc[k * 24 + c];
    out[c] = tanhf(acc);
}

// ---------------- launch ----------------
extern "C" void kernel_launch(void* const* d_in, const int* in_sizes, int n_in,
                              void* d_out, int out_size) {
    const float* x   = (const float*)d_in[0];
    const int*   ei  = (const int*)d_in[1];   // int32 (JAX x64 disabled)
    const float* W1  = (const float*)d_in[3];
    const float* b1  = (const float*)d_in[4];
    const float* W2  = (const float*)d_in[5];
    const float* b2  = (const float*)d_in[6];
    const float* W3  = (const float*)d_in[7];
    const float* b3  = (const float*)d_in[8];
    const float* Wfc = (const float*)d_in[9];
    const float* bfc = (const float*)d_in[10];
    float* out = (float*)d_out;

    int N = in_sizes[0] / 3;
    int E = in_sizes[1] / 2;

    const int T = 256;
    int nbN    = (N + T - 1) / T;
    int nbE    = (E + T - 1) / T;
    int nbTr   = (N + 63) / 64;
    int nbScan = (N + SCAN_ITEMS - 1) / SCAN_ITEMS;

    // CSR + normalization
    k_zero<<<nbN, T>>>(N);
    k_hist<<<nbE, T>>>(ei, E);
    k_prep<<<nbN, T>>>(x, N);
    k_scan_local<<<nbScan, SCAN_T>>>(N);
    k_scan_bsums<<<1, SCAN_T>>>(nbScan);
    k_scan_add<<<nbN, T>>>(N, E);
    k_fill<<<nbE, T>>>(ei, E);

    // layer 1 aggregation (float4 rows)
    k_agg_x<<<nbN, T>>>(N);

    // fused layer1+layer2 transforms -> m0 (tf32 tensor cores)
    kA_l12<<<nbTr, T>>>(W1, b1, W2, N);

    // fused layer2 aggregation + layer3 transform -> m1 (tf32 tensor cores)
    kB_agg_tr<<<nbTr, T>>>(b2, W3, N);

    // fused layer3 aggregation + relu + mean-pool
    kC_agg_pool<<<POOL_BLOCKS, T>>>(b3, N);

    // reduce + FC + tanh
    k_reduce<<<64, 256>>>(POOL_BLOCKS);
    k_final<<<1, 32>>>(Wfc, bfc, out, N);
}

// round 11
// speedup vs baseline: 6.3831x; 1.0210x over previous
#include <cuda_runtime.h>
#include <cuda_bf16.h>
#include <cstdint>
#include <math.h>

#define MAX_N 500000
#define MAX_E 1000000
#define HDIM  64
#define SCAN_T 512
#define SCAN_ITEMS 1024
#define POOL_BLOCKS 2960

// ---------------- device scratch ----------------
__device__ __nv_bfloat16 g_m0[(size_t)MAX_N * HDIM];  // layer-2 messages (bf16)
__device__ __nv_bfloat16 g_m1[(size_t)MAX_N * HDIM];  // layer-3 messages (bf16)
__device__ float g_dinv[MAX_N];
__device__ float4 g_xs4[MAX_N];
__device__ int   g_degi[MAX_N];
__device__ int   g_rowptr[MAX_N + 1];
__device__ int   g_cursor[MAX_N];
__device__ int   g_esrc[MAX_E];
__device__ int   g_bsum[1024];
__device__ float g_partial[(size_t)POOL_BLOCKS * HDIM];
__device__ float g_pool[HDIM];

// ---------------- helpers ----------------
__device__ __forceinline__ unsigned pack_bf16x2(float lo, float hi) {
    unsigned r;
    asm("cvt.rn.bf16x2.f32 %0, %1, %2;" : "=r"(r) : "f"(hi), "f"(lo));
    return r;
}
__device__ __forceinline__ void acc_bf16x2(float& a0, float& a1, unsigned v) {
    __nv_bfloat162 b = *reinterpret_cast<__nv_bfloat162*>(&v);
    float2 f = __bfloat1622float2(b);
    a0 += f.x; a1 += f.y;
}
__device__ __forceinline__ void acc_uint4(float* a, uint4 v) {
    acc_bf16x2(a[0], a[1], v.x);
    acc_bf16x2(a[2], a[3], v.y);
    acc_bf16x2(a[4], a[5], v.z);
    acc_bf16x2(a[6], a[7], v.w);
}
__device__ __forceinline__ uint32_t f2tf32(float f) {
    uint32_t r;
    asm("cvt.rna.tf32.f32 %0, %1;" : "=r"(r) : "f"(f));
    return r;
}
__device__ __forceinline__ void mma_tf32(float* d, uint32_t a0, uint32_t a1, uint32_t a2,
                                         uint32_t a3, uint32_t b0, uint32_t b1) {
    asm volatile("mma.sync.aligned.m16n8k8.row.col.f32.tf32.tf32.f32 "
                 "{%0,%1,%2,%3}, {%4,%5,%6,%7}, {%8,%9}, {%0,%1,%2,%3};"
                 : "+f"(d[0]), "+f"(d[1]), "+f"(d[2]), "+f"(d[3])
                 : "r"(a0), "r"(a1), "r"(a2), "r"(a3), "r"(b0), "r"(b1));
}

#define AROW 68   // fp32/tf32 smem row stride (u32)

// ---------------- degree / CSR ----------------
__global__ void k_zero(int N) {
    int i = blockIdx.x * blockDim.x + threadIdx.x;
    if (i < N) { g_degi[i] = 0; g_cursor[i] = 0; }
}

__global__ void k_hist(const int* __restrict__ ei, int E) {
    int e = blockIdx.x * blockDim.x + threadIdx.x;
    if (e < E) atomicAdd(&g_degi[ei[E + e]], 1);
}

__global__ __launch_bounds__(SCAN_T) void k_scan_local(int N) {
    __shared__ int sdata[SCAN_T];
    int base = blockIdx.x * SCAN_ITEMS;
    int i0 = base + threadIdx.x * 2;
    int d0 = (i0     < N) ? g_degi[i0]     : 0;
    int d1 = (i0 + 1 < N) ? g_degi[i0 + 1] : 0;
    int tsum = d0 + d1;
    sdata[threadIdx.x] = tsum;
    __syncthreads();
    for (int off = 1; off < SCAN_T; off <<= 1) {
        int v = (threadIdx.x >= off) ? sdata[threadIdx.x - off] : 0;
        __syncthreads();
        sdata[threadIdx.x] += v;
        __syncthreads();
    }
    int excl = sdata[threadIdx.x] - tsum;
    if (i0     < N) g_rowptr[i0]     = excl;
    if (i0 + 1 < N) g_rowptr[i0 + 1] = excl + d0;
    if (threadIdx.x == SCAN_T - 1) g_bsum[blockIdx.x] = sdata[SCAN_T - 1];
}

__global__ __launch_bounds__(SCAN_T) void k_scan_bsums(int B) {
    __shared__ int sdata[SCAN_T];
    int v = (threadIdx.x < B) ? g_bsum[threadIdx.x] : 0;
    sdata[threadIdx.x] = v;
    __syncthreads();
    for (int off = 1; off < SCAN_T; off <<= 1) {
        int p = (threadIdx.x >= off) ? sdata[threadIdx.x - off] : 0;
        __syncthreads();
        sdata[threadIdx.x] += p;
        __syncthreads();
    }
    if (threadIdx.x < B) g_bsum[threadIdx.x] = sdata[threadIdx.x] - v;
}

// merged: finish scan + compute dinv + scaled x rows
__global__ void k_scan_add_prep(const float* __restrict__ x, int N, int E) {
    int i = blockIdx.x * blockDim.x + threadIdx.x;
    if (i == 0) g_rowptr[N] = E;
    if (i >= N) return;
    g_rowptr[i] += g_bsum[i / SCAN_ITEMS];
    float di = rsqrtf((float)(g_degi[i] + 1));
    g_dinv[i] = di;
    g_xs4[i] = make_float4(di * x[(size_t)i * 3 + 0],
                           di * x[(size_t)i * 3 + 1],
                           di * x[(size_t)i * 3 + 2], 0.0f);
}

__global__ void k_fill(const int* __restrict__ ei, int E) {
    int e = blockIdx.x * blockDim.x + threadIdx.x;
    if (e >= E) return;
    int s = ei[e];
    int d = ei[E + e];
    int pos = g_rowptr[d] + atomicAdd(&g_cursor[d], 1);
    g_esrc[pos] = s;
}

// ---------------- tf32 tensor-core GEMM phase ----------------
__device__ __forceinline__ void gemm_mma(const uint32_t* sA, const uint32_t* sB,
                                         uint32_t* sC, const float* sdinv,
                                         __nv_bfloat16* outBuf, int nodeBase, int N) {
    int tid  = threadIdx.x;
    int w    = tid >> 5;
    int lane = tid & 31;
    int mw = w & 3;
    int nw = w >> 2;
    int g  = lane >> 2;
    int t  = lane & 3;

    float d[4][4];
    #pragma unroll
    for (int i = 0; i < 4; i++)
        #pragma unroll
        for (int j = 0; j < 4; j++) d[i][j] = 0.0f;

    const uint32_t* aRow0 = sA + (mw * 16 + g) * AROW;
    const uint32_t* aRow1 = aRow0 + 8 * AROW;
    int nbase = nw * 32 + g;

    #pragma unroll
    for (int kt = 0; kt < 8; kt++) {
        int k0 = kt * 8 + t;
        uint32_t a0 = aRow0[k0];
        uint32_t a1 = aRow1[k0];
        uint32_t a2 = aRow0[k0 + 4];
        uint32_t a3 = aRow1[k0 + 4];
        const uint32_t* b0p = sB + k0 * AROW + nbase;
        const uint32_t* b1p = b0p + 4 * AROW;
        #pragma unroll
        for (int nt = 0; nt < 4; nt++) {
            mma_tf32(d[nt], a0, a1, a2, a3, b0p[nt * 8], b1p[nt * 8]);
        }
    }

    int r0 = mw * 16 + g;
    int r1 = r0 + 8;
    float di0 = sdinv[r0], di1 = sdinv[r1];
    #pragma unroll
    for (int nt = 0; nt < 4; nt++) {
        int cp = nw * 16 + nt * 4 + t;
        sC[r0 * 36 + cp] = pack_bf16x2(d[nt][0] * di0, d[nt][1] * di0);
        sC[r1 * 36 + cp] = pack_bf16x2(d[nt][2] * di1, d[nt][3] * di1);
    }
    __syncthreads();

    int r = tid >> 2, q = tid & 3;
    if (nodeBase + r < N) {
        uint4 v0 = *(uint4*)&sC[r * 36 + q * 8];
        uint4 v1 = *(uint4*)&sC[r * 36 + q * 8 + 4];
        __nv_bfloat16* o = outBuf + (size_t)(nodeBase + r) * HDIM + q * 16;
        *(uint4*)o       = v0;
        *((uint4*)o + 1) = v1;
    }
}

__device__ __forceinline__ void load_W_tf32(const float* __restrict__ W, uint32_t* sB) {
    int tid = threadIdx.x;
    #pragma unroll
    for (int i = tid; i < 1024; i += 256) {
        int k = i >> 4, cq = i & 15;
        float4 wv = ((const float4*)W)[i];
        uint32_t* o = sB + k * AROW + cq * 4;
        o[0] = f2tf32(wv.x); o[1] = f2tf32(wv.y);
        o[2] = f2tf32(wv.z); o[3] = f2tf32(wv.w);
    }
}

__device__ __forceinline__ void load_dinv(float* sdinv, int nodeBase, int N) {
    int tid = threadIdx.x;
    if (tid >= 64 && tid < 128) {
        int n = nodeBase + tid - 64;
        sdinv[tid - 64] = (n < N) ? g_dinv[n] : 0.0f;
    }
}

// ---------------- kA: fused x-aggregation + layer-1 + layer-2 transforms -> m0 ----------------
__global__ __launch_bounds__(256) void kA_l12(const float* __restrict__ W1,
                                              const float* __restrict__ b1,
                                              const float* __restrict__ W2, int N) {
    __shared__ __align__(16) uint32_t sA[64 * AROW];
    __shared__ __align__(16) uint32_t sB[64 * AROW];
    __shared__ __align__(16) uint32_t sC[64 * 36];
    __shared__ float4 sxa[64];
    __shared__ float sW1[192];
    __shared__ float sb1[64];
    __shared__ float sdinv[64];
    int tid = threadIdx.x;
    int nodeBase = blockIdx.x * 64;

    // lanes 0..63: aggregate x for own node (pair-batched gathers)
    if (tid < 64) {
        int d = nodeBase + tid;
        float4 a = make_float4(0.f, 0.f, 0.f, 0.f);
        float di = 0.0f;
        if (d < N) {
            a = g_xs4[d];
            int i = g_rowptr[d], end = g_rowptr[d + 1];
            for (; i + 2 <= end; i += 2) {
                int s0 = g_esrc[i], s1 = g_esrc[i + 1];
                float4 v0 = g_xs4[s0];
                float4 v1 = g_xs4[s1];
                a.x += v0.x + v1.x; a.y += v0.y + v1.y; a.z += v0.z + v1.z;
            }
            if (i < end) {
                float4 v = g_xs4[g_esrc[i]];
                a.x += v.x; a.y += v.y; a.z += v.z;
            }
            di = g_dinv[d];
        }
        sxa[tid] = make_float4(di * a.x, di * a.y, di * a.z, 0.0f);
    }
    if (tid >= 192) {
        int j = tid - 192;
        if (j < 64) sb1[j] = b1[j];
    }
    if (tid >= 128 && tid < 192) {
        sW1[tid - 128] = W1[tid - 128];
        sW1[tid - 64]  = W1[tid - 64];
        sW1[tid]       = W1[tid];
    }
    load_dinv(sdinv, nodeBase, N);
    load_W_tf32(W2, sB);
    __syncthreads();

    // phase 1: sA[n][c] = tf32(relu(xa @ W1 + b1))
    #pragma unroll
    for (int i = tid; i < 4096; i += 256) {
        int n = i >> 6, c = i & 63;
        float4 xa = sxa[n];
        float v = sb1[c] + xa.x * sW1[c] + xa.y * sW1[64 + c] + xa.z * sW1[128 + c];
        sA[n * AROW + c] = f2tf32(fmaxf(v, 0.0f));
    }
    __syncthreads();

    gemm_mma(sA, sB, sC, sdinv, g_m0, nodeBase, N);
}

// ---------------- kB: fused layer-2 aggregation + layer-3 transform -> m1 ----------------
__global__ __launch_bounds__(256) void kB_agg_tr(const float* __restrict__ b2,
                                                 const float* __restrict__ W3, int N) {
    __shared__ __align__(16) uint32_t sA[64 * AROW];
    __shared__ __align__(16) uint32_t sB[64 * AROW];
    __shared__ __align__(16) uint32_t sC[64 * 36];
    __shared__ float sb2[64];
    __shared__ float sdinv[64];
    int tid = threadIdx.x;
    int nodeBase = blockIdx.x * 64;

    if (tid < 64) sb2[tid] = b2[tid];
    load_dinv(sdinv, nodeBase, N);
    load_W_tf32(W3, sB);

    // aggregation: octet per node row, pair-batched edge gathers (uint4 = 8 bf16)
    {
        int w    = tid >> 5;
        int lane = tid & 31;
        int oct  = lane >> 3;
        int l8   = lane & 7;
        #pragma unroll
        for (int j = 0; j < 2; j++) {
            int nl = w * 8 + j * 4 + oct;
            int d  = nodeBase + nl;
            float a[8] = {0.f, 0.f, 0.f, 0.f, 0.f, 0.f, 0.f, 0.f};
            float di = 0.0f;
            if (d < N) {
                acc_uint4(a, ((const uint4*)(g_m0 + (size_t)d * HDIM))[l8]);
                int i = g_rowptr[d], end = g_rowptr[d + 1];
                for (; i + 2 <= end; i += 2) {
                    int s0 = g_esrc[i], s1 = g_esrc[i + 1];
                    uint4 u0 = ((const uint4*)(g_m0 + (size_t)s0 * HDIM))[l8];
                    uint4 u1 = ((const uint4*)(g_m0 + (size_t)s1 * HDIM))[l8];
                    acc_uint4(a, u0);
                    acc_uint4(a, u1);
                }
                if (i < end) {
                    int s = g_esrc[i];
                    acc_uint4(a, ((const uint4*)(g_m0 + (size_t)s * HDIM))[l8]);
                }
                di = g_dinv[d];
            }
            const float* bb = &sb2[l8 * 8];
            uint32_t* o = sA + nl * AROW + l8 * 8;
            #pragma unroll
            for (int k = 0; k < 8; k++)
                o[k] = f2tf32(fmaxf(bb[k] + di * a[k], 0.f));
        }
    }
    __syncthreads();

    gemm_mma(sA, sB, sC, sdinv, g_m1, nodeBase, N);
}

// ---------------- kC: fused layer-3 aggregation + relu + pool partials ----------------
__global__ __launch_bounds__(256) void kC_agg_pool(const float* __restrict__ b, int N) {
    int tid  = threadIdx.x;
    int w    = tid >> 5;
    int lane = tid & 31;
    int oct  = lane >> 3;
    int l8   = lane & 7;

    float bb[8];
    #pragma unroll
    for (int k = 0; k < 8; k++) bb[k] = b[l8 * 8 + k];
    float acc[8] = {0.f, 0.f, 0.f, 0.f, 0.f, 0.f, 0.f, 0.f};

    int stride = gridDim.x * 32;
    for (int d = blockIdx.x * 32 + w * 4 + oct; d < N; d += stride) {
        float a[8] = {0.f, 0.f, 0.f, 0.f, 0.f, 0.f, 0.f, 0.f};
        acc_uint4(a, ((const uint4*)(g_m1 + (size_t)d * HDIM))[l8]);
        int i = g_rowptr[d], end = g_rowptr[d + 1];
        for (; i + 2 <= end; i += 2) {
            int s0 = g_esrc[i], s1 = g_esrc[i + 1];
            uint4 u0 = ((const uint4*)(g_m1 + (size_t)s0 * HDIM))[l8];
            uint4 u1 = ((const uint4*)(g_m1 + (size_t)s1 * HDIM))[l8];
            acc_uint4(a, u0);
            acc_uint4(a, u1);
        }
        if (i < end) {
            int s = g_esrc[i];
            acc_uint4(a, ((const uint4*)(g_m1 + (size_t)s * HDIM))[l8]);
        }
        float di = g_dinv[d];
        #pragma unroll
        for (int k = 0; k < 8; k++)
            acc[k] += fmaxf(bb[k] + di * a[k], 0.f);
    }

    __shared__ float sp[64];
    if (tid < 64) sp[tid] = 0.0f;
    __syncthreads();
    #pragma unroll
    for (int k = 0; k < 8; k++)
        atomicAdd(&sp[l8 * 8 + k], acc[k]);
    __syncthreads();
    if (tid < 64) g_partial[(size_t)blockIdx.x * HDIM + tid] = sp[tid];
}

__global__ __launch_bounds__(256) void k_reduce(int numPartial) {
    __shared__ float sdata[256];
    int c = blockIdx.x;
    float s = 0.0f;
    for (int i = threadIdx.x; i < numPartial; i += 256)
        s += g_partial[(size_t)i * HDIM + c];
    sdata[threadIdx.x] = s;
    __syncthreads();
    for (int off = 128; off > 0; off >>= 1) {
        if (threadIdx.x < off) sdata[threadIdx.x] += sdata[threadIdx.x + off];
        __syncthreads();
    }
    if (threadIdx.x == 0) g_pool[c] = sdata[0];
}

__global__ void k_final(const float* __restrict__ Wfc, const float* __restrict__ bfc,
                        float* __restrict__ out, int N) {
    int c = threadIdx.x;
    if (c >= 24) return;
    float invN = 1.0f / (float)N;
    float acc = bfc[c];
    #pragma unroll
    for (int k = 0; k < 64; k++)
        acc += (g_pool[k] * invN) * Wfc[k * 24 + c];
    out[c] = tanhf(acc);
}

// ---------------- launch ----------------
extern "C" void kernel_launch(void* const* d_in, const int* in_sizes, int n_in,
                              void* d_out, int out_size) {
    const float* x   = (const float*)d_in[0];
    const int*   ei  = (const int*)d_in[1];   // int32 (JAX x64 disabled)
    const float* W1  = (const float*)d_in[3];
    const float* b1  = (const float*)d_in[4];
    const float* W2  = (const float*)d_in[5];
    const float* b2  = (const float*)d_in[6];
    const float* W3  = (const float*)d_in[7];
    const float* b3  = (const float*)d_in[8];
    const float* Wfc = (const float*)d_in[9];
    const float* bfc = (const float*)d_in[10];
    float* out = (float*)d_out;

    int N = in_sizes[0] / 3;
    int E = in_sizes[1] / 2;

    const int T = 256;
    int nbN    = (N + T - 1) / T;
    int nbE    = (E + T - 1) / T;
    int nbTr   = (N + 63) / 64;
    int nbScan = (N + SCAN_ITEMS - 1) / SCAN_ITEMS;

    // CSR + normalization
    k_zero<<<nbN, T>>>(N);
    k_hist<<<nbE, T>>>(ei, E);
    k_scan_local<<<nbScan, SCAN_T>>>(N);
    k_scan_bsums<<<1, SCAN_T>>>(nbScan);
    k_scan_add_prep<<<nbN, T>>>(x, N, E);
    k_fill<<<nbE, T>>>(ei, E);

    // fused x-agg + layer1 + layer2 transforms -> m0 (tf32 tensor cores)
    kA_l12<<<nbTr, T>>>(W1, b1, W2, N);

    // fused layer2 aggregation + layer3 transform -> m1 (tf32 tensor cores)
    kB_agg_tr<<<nbTr, T>>>(b2, W3, N);

    // fused layer3 aggregation + relu + mean-pool
    kC_agg_pool<<<POOL_BLOCKS, T>>>(b3, N);

    // reduce + FC + tanh
    k_reduce<<<64, 256>>>(POOL_BLOCKS);
    k_final<<<1, 32>>>(Wfc, bfc, out, N);
}